// round 1
// baseline (speedup 1.0000x reference)
#include <cuda_runtime.h>
#include <cuda_bf16.h>
#include <cstdint>

// CategorySpecificLinear: out[n,m,h] = sum_k x[n,m,k] * W[cat[n],k,h] + b[cat[n],h]
// N=4096, M=16, K=256, H=256, 64 categories.
//
// Round 0 baseline: fp32 FFMA kernel, one CTA per sample.
//  - x sample (16x256 f32 = 16KB) staged in smem, read as broadcast LDS.128
//  - W streamed from global (hot in L2: W is only 16MB total, reused ~64x)
//  - thread = output column h; 16 fp32 accumulators (one per m-row)
//  - inner loop: per 4 k's -> 4 coalesced LDG (W) + 16 LDS.128 (x) + 64 FFMA

#define M_ROWS 16
#define K_DIM  256
#define H_DIM  256
#define MAX_N  4096

__device__ int g_cat[MAX_N];

// Decode cat_ids robustly whether the buffer is int32 or int64 (little-endian).
// If int64: every odd 32-bit word is the high half of a value in [0,64) -> 0.
// If int32: odd words are cat_ids[1,3,5,...]; all-zero is probabilistically nil.
__global__ void decode_cats_kernel(const int* __restrict__ raw, int n) {
    __shared__ int odd_nonzero;
    if (threadIdx.x == 0) odd_nonzero = 0;
    __syncthreads();
    int local = 0;
    for (int i = threadIdx.x; i < n / 2; i += blockDim.x)
        local |= raw[2 * i + 1];
    if (local) atomicOr(&odd_nonzero, 1);
    __syncthreads();
    bool is64 = (odd_nonzero == 0);
    for (int i = threadIdx.x; i < n; i += blockDim.x)
        g_cat[i] = is64 ? raw[2 * i] : raw[i];
}

__global__ __launch_bounds__(256, 8)
void cat_linear_kernel(const float* __restrict__ x,
                       const float* __restrict__ W,
                       const float* __restrict__ b,
                       float* __restrict__ out) {
    const int n = blockIdx.x;
    const int h = threadIdx.x;

    // Stage this sample's x [16,256] into smem as float4 (16 KB).
    __shared__ float4 xs4[M_ROWS * (K_DIM / 4)];  // [m][k4]
    const float4* xsrc = reinterpret_cast<const float4*>(x + (size_t)n * M_ROWS * K_DIM);
    #pragma unroll
    for (int i = threadIdx.x; i < M_ROWS * (K_DIM / 4); i += 256)
        xs4[i] = xsrc[i];

    const int cat = g_cat[n];
    const float* Wp = W + (size_t)cat * K_DIM * H_DIM + h;  // column h, stride H_DIM
    const float bias = b[cat * H_DIM + h];

    float acc[M_ROWS];
    #pragma unroll
    for (int m = 0; m < M_ROWS; m++) acc[m] = bias;

    __syncthreads();

    // Main loop over K in chunks of 4.
    #pragma unroll 2
    for (int k4 = 0; k4 < K_DIM / 4; k4++) {
        const float w0 = __ldg(Wp + (4 * k4 + 0) * H_DIM);
        const float w1 = __ldg(Wp + (4 * k4 + 1) * H_DIM);
        const float w2 = __ldg(Wp + (4 * k4 + 2) * H_DIM);
        const float w3 = __ldg(Wp + (4 * k4 + 3) * H_DIM);
        #pragma unroll
        for (int m = 0; m < M_ROWS; m++) {
            const float4 xv = xs4[m * (K_DIM / 4) + k4];  // broadcast LDS.128
            acc[m] = fmaf(xv.x, w0, acc[m]);
            acc[m] = fmaf(xv.y, w1, acc[m]);
            acc[m] = fmaf(xv.z, w2, acc[m]);
            acc[m] = fmaf(xv.w, w3, acc[m]);
        }
    }

    float* op = out + (size_t)n * M_ROWS * H_DIM + h;
    #pragma unroll
    for (int m = 0; m < M_ROWS; m++)
        op[m * H_DIM] = acc[m];
}

extern "C" void kernel_launch(void* const* d_in, const int* in_sizes, int n_in,
                              void* d_out, int out_size) {
    const float* x   = (const float*)d_in[0];
    const int*   cid = (const int*)d_in[1];   // int32 or int64 raw words; decoded below
    const float* W   = (const float*)d_in[2];
    const float* b   = (const float*)d_in[3];
    float* out = (float*)d_out;

    const int N = in_sizes[0] / (M_ROWS * K_DIM);  // 4096

    decode_cats_kernel<<<1, 256>>>(cid, N);
    cat_linear_kernel<<<N, 256>>>(x, W, b, out);
}

// round 4
// speedup vs baseline: 1.5521x; 1.5521x over previous
#include <cuda_runtime.h>
#include <cuda_bf16.h>
#include <cstdint>

// CategorySpecificLinear on sm_103 (family target -- no tcgen05 available):
// out[n,m,h] = sum_k x[n,m,k] * W[cat[n],k,h] + b[cat[n],h]
// N=4096, M=16, K=256, H=256, 64 categories.
//
// Counting-sort samples by category -> tiles of 8 samples (M=128 rows).
// Each CTA: M=128 x N=256(H), K=256 in 4 chunks of 64.
// mma.sync.m16n8k16 bf16 with 3-term split (xh*Wh + xh*Wl + xl*Wh), fp32 acc.
// W pre-transposed+split to bf16 [cat][h][k]; double-buffered via cp.async.

#define K_DIM   256
#define H_DIM   256
#define M_ROWS  16
#define MAX_N   4096
#define NCAT    64
#define MAX_TILES (MAX_N / 8 + NCAT)     // 576
#define KC      64

__device__ int g_cat[MAX_N];
__device__ int g_pad_sorted[MAX_TILES * 8];
__device__ int g_tile_cat[MAX_TILES];
__device__ int g_num_tiles;
__device__ __nv_bfloat16 g_Wt_hi[NCAT * H_DIM * K_DIM];  // [cat][h][k]
__device__ __nv_bfloat16 g_Wt_lo[NCAT * H_DIM * K_DIM];

// ---------------- smem layout (bytes) ----------------
#define SM_IDS    0              // 8 ints
#define SM_BIAS   64             // 256 f32
#define SM_A_HI   2048           // 128x64 bf16 = 16KB
#define SM_A_LO   (SM_A_HI + 16384)
#define SM_B0     (SM_A_LO + 16384)    // 34816; per buf: hi 32KB + lo 32KB
#define SM_BUF_SZ 65536
#define SM_TOTAL  (SM_B0 + 2 * SM_BUF_SZ)   // 165888
#define SM_STAGE  SM_A_HI        // epilogue: 128x66 f32 = 33792 (A + dead B0 head)

#define SWZ(row, c) (((uint32_t)(row)) * 128u + (((uint32_t)(c)) ^ ((((uint32_t)(row)) & 7u) << 4)))

__device__ __forceinline__ uint32_t smem_u32(const void* p) {
    uint32_t a;
    asm("{ .reg .u64 t; cvta.to.shared.u64 t, %1; cvt.u32.u64 %0, t; }" : "=r"(a) : "l"(p));
    return a;
}

#define CP_ASYNC16(dst, src) \
    asm volatile("cp.async.cg.shared.global [%0], [%1], 16;" :: "r"(dst), "l"(src) : "memory")
#define CP_COMMIT() asm volatile("cp.async.commit_group;" ::: "memory")
#define CP_WAIT(n)  asm volatile("cp.async.wait_group %0;" :: "n"(n) : "memory")

__device__ __forceinline__ void mma_bf16(float* d, const uint32_t* a, uint32_t b0, uint32_t b1) {
    asm volatile(
        "mma.sync.aligned.m16n8k16.row.col.f32.bf16.bf16.f32 "
        "{%0,%1,%2,%3}, {%4,%5,%6,%7}, {%8,%9}, {%0,%1,%2,%3};"
        : "+f"(d[0]), "+f"(d[1]), "+f"(d[2]), "+f"(d[3])
        : "r"(a[0]), "r"(a[1]), "r"(a[2]), "r"(a[3]), "r"(b0), "r"(b1));
}

// ---------------- Prep: decode cat_ids + counting sort into 8-sample tiles ----------------
__global__ void prep_kernel(const int* __restrict__ raw, int n) {
    __shared__ int cnt[NCAT], curs[NCAT], padoff[NCAT], oddnz;
    int t = threadIdx.x;
    if (t == 0) oddnz = 0;
    for (int c = t; c < NCAT; c += blockDim.x) { cnt[c] = 0; curs[c] = 0; }
    __syncthreads();
    int local = 0;
    for (int i = t; i < n / 2; i += blockDim.x) local |= raw[2 * i + 1];
    if (local) atomicOr(&oddnz, 1);
    __syncthreads();
    bool is64 = (oddnz == 0);
    for (int i = t; i < n; i += blockDim.x) {
        int c = is64 ? raw[2 * i] : raw[i];
        g_cat[i] = c;
        atomicAdd(&cnt[c], 1);
    }
    for (int i = t; i < MAX_TILES * 8; i += blockDim.x) g_pad_sorted[i] = -1;
    __syncthreads();
    if (t == 0) {
        int po = 0;
        for (int c = 0; c < NCAT; c++) {
            padoff[c] = po;
            int nt = (cnt[c] + 7) / 8;
            for (int tt = 0; tt < nt; tt++) g_tile_cat[po / 8 + tt] = c;
            po += nt * 8;
        }
        g_num_tiles = po / 8;
    }
    __syncthreads();
    for (int i = t; i < n; i += blockDim.x) {
        int c = g_cat[i];
        int p = atomicAdd(&curs[c], 1);
        g_pad_sorted[padoff[c] + p] = i;
    }
}

// ---------------- Prep: W [cat][k][h] f32 -> Wt_{hi,lo} [cat][h][k] bf16 ----------------
__global__ void wconv_kernel(const float* __restrict__ W) {
    __shared__ float tile[32][33];
    int cat = blockIdx.z, ht = blockIdx.x, kt = blockIdx.y;
    int tx = threadIdx.x, ty = threadIdx.y;  // (32, 8)
    const float* Wc = W + (size_t)cat * K_DIM * H_DIM;
    #pragma unroll
    for (int j = 0; j < 4; j++) {
        int k = kt * 32 + ty + j * 8, h = ht * 32 + tx;
        tile[ty + j * 8][tx] = Wc[k * H_DIM + h];
    }
    __syncthreads();
    size_t base = (size_t)cat * H_DIM * K_DIM;
    #pragma unroll
    for (int j = 0; j < 4; j++) {
        int h = ht * 32 + ty + j * 8, k = kt * 32 + tx;
        float v = tile[tx][ty + j * 8];
        __nv_bfloat16 hi = __float2bfloat16_rn(v);
        __nv_bfloat16 lo = __float2bfloat16_rn(v - __bfloat162float(hi));
        g_Wt_hi[base + (size_t)h * K_DIM + k] = hi;
        g_Wt_lo[base + (size_t)h * K_DIM + k] = lo;
    }
}

// ---------------- GEMM ----------------
__global__ void __launch_bounds__(256, 1)
gemm_kernel(const float* __restrict__ x, const float* __restrict__ b,
            float* __restrict__ out) {
    extern __shared__ char smem[];
    const int tile = blockIdx.x;
    if (tile >= g_num_tiles) return;

    const uint32_t sbase = smem_u32(smem);
    const int tid = threadIdx.x;
    const int wid = tid >> 5, lid = tid & 31;
    const int wm = wid >> 1, wn = wid & 1;        // 4M x 2N warp grid
    const int g = lid >> 2, tig = lid & 3;
    const uint32_t gx = (uint32_t)g << 4;
    const int cat = g_tile_cat[tile];

    int* ids_s = (int*)(smem + SM_IDS);
    float* b_s = (float*)(smem + SM_BIAS);
    if (tid < 8) ids_s[tid] = g_pad_sorted[tile * 8 + tid];
    b_s[tid] = b[cat * H_DIM + tid];
    __syncthreads();

    const __nv_bfloat16* WtH = g_Wt_hi + (size_t)cat * H_DIM * K_DIM;
    const __nv_bfloat16* WtL = g_Wt_lo + (size_t)cat * H_DIM * K_DIM;

    float acc[2][16][4];
    #pragma unroll
    for (int ma = 0; ma < 2; ma++)
        #pragma unroll
        for (int na = 0; na < 16; na++)
            #pragma unroll
            for (int r = 0; r < 4; r++) acc[ma][na][r] = 0.f;

    // ---- B chunk loader: 256 rows x 64 k (hi + lo), cp.async 16B ----
    auto issueB = [&](int kc, int buf) {
        const uint32_t bh = sbase + SM_B0 + buf * SM_BUF_SZ;
        const uint32_t bl = bh + 32768;
        const int k0 = kc * KC;
        #pragma unroll
        for (int j = 0; j < 4; j++) {               // 1024 iters / 256 threads
            int i = tid + j * 256;
            int row = i >> 2, u = i & 3;            // 4 x 16B per row... (only 64B!?)
            // row covers 0..255 with 4 x 16B = 64B per row? No: 64 k bf16 = 128B
            // -> 8 x 16B per row; redo indexing below.
            (void)row; (void)u;
        }
        // 256 rows x 8 x 16B = 2048 ops per piece; 8 per thread per piece
        #pragma unroll
        for (int j = 0; j < 8; j++) {
            int i = tid + j * 256;
            int row = i >> 3, u = i & 7;
            uint32_t off = SWZ(row, u * 16);
            const char* srcH = (const char*)(WtH + (size_t)row * K_DIM + k0) + u * 16;
            const char* srcL = (const char*)(WtL + (size_t)row * K_DIM + k0) + u * 16;
            CP_ASYNC16(bh + off, srcH);
            CP_ASYNC16(bl + off, srcL);
        }
    };

    // ---- A chunk convert: x f32 -> A_hi/A_lo bf16 (128 rows x 64 k) ----
    auto convertA = [&](int kc) {
        const int k0 = kc * KC;
        #pragma unroll
        for (int j = 0; j < 8; j++) {               // 2048 / 256
            int i = tid + j * 256;
            int row = i >> 4, f4 = i & 15;
            int id = ids_s[row >> 4];
            float4 v = make_float4(0.f, 0.f, 0.f, 0.f);
            if (id >= 0)
                v = *reinterpret_cast<const float4*>(
                        x + (size_t)id * (M_ROWS * K_DIM) + (row & 15) * K_DIM + k0 + f4 * 4);
            __nv_bfloat16 hx = __float2bfloat16_rn(v.x), hy = __float2bfloat16_rn(v.y);
            __nv_bfloat16 hz = __float2bfloat16_rn(v.z), hw = __float2bfloat16_rn(v.w);
            __nv_bfloat162 h01 = __halves2bfloat162(hx, hy), h23 = __halves2bfloat162(hz, hw);
            __nv_bfloat162 l01 = __halves2bfloat162(
                __float2bfloat16_rn(v.x - __bfloat162float(hx)),
                __float2bfloat16_rn(v.y - __bfloat162float(hy)));
            __nv_bfloat162 l23 = __halves2bfloat162(
                __float2bfloat16_rn(v.z - __bfloat162float(hz)),
                __float2bfloat16_rn(v.w - __bfloat162float(hw)));
            uint32_t off = SWZ(row, f4 * 8);
            *reinterpret_cast<uint2*>(smem + SM_A_HI + off) =
                make_uint2(*(uint32_t*)&h01, *(uint32_t*)&h23);
            *reinterpret_cast<uint2*>(smem + SM_A_LO + off) =
                make_uint2(*(uint32_t*)&l01, *(uint32_t*)&l23);
        }
    };

    issueB(0, 0);
    CP_COMMIT();

    for (int kc = 0; kc < 4; kc++) {
        convertA(kc);
        if (kc < 3) {
            issueB(kc + 1, (kc + 1) & 1);
            CP_COMMIT();
            CP_WAIT(1);
        } else {
            CP_WAIT(0);
        }
        __syncthreads();

        // ---- compute chunk ----
        const uint32_t aH = sbase + SM_A_HI, aL = sbase + SM_A_LO;
        const uint32_t bH = sbase + SM_B0 + (kc & 1) * SM_BUF_SZ;
        const uint32_t bL = bH + 32768;
        #pragma unroll
        for (int ks = 0; ks < 4; ks++) {
            const uint32_t c0 = ((uint32_t)(ks * 32 + tig * 4)) ^ gx;
            const uint32_t c1 = ((uint32_t)(ks * 32 + tig * 4 + 16)) ^ gx;
            uint32_t ahi[2][4], alo[2][4];
            #pragma unroll
            for (int ma = 0; ma < 2; ma++) {
                const uint32_t r0 = (uint32_t)(wm * 32 + ma * 16 + g) * 128u;
                const uint32_t r8 = r0 + 8u * 128u;
                asm volatile("ld.shared.b32 %0, [%1];" : "=r"(ahi[ma][0]) : "r"(aH + r0 + c0));
                asm volatile("ld.shared.b32 %0, [%1];" : "=r"(ahi[ma][1]) : "r"(aH + r8 + c0));
                asm volatile("ld.shared.b32 %0, [%1];" : "=r"(ahi[ma][2]) : "r"(aH + r0 + c1));
                asm volatile("ld.shared.b32 %0, [%1];" : "=r"(ahi[ma][3]) : "r"(aH + r8 + c1));
                asm volatile("ld.shared.b32 %0, [%1];" : "=r"(alo[ma][0]) : "r"(aL + r0 + c0));
                asm volatile("ld.shared.b32 %0, [%1];" : "=r"(alo[ma][1]) : "r"(aL + r8 + c0));
                asm volatile("ld.shared.b32 %0, [%1];" : "=r"(alo[ma][2]) : "r"(aL + r0 + c1));
                asm volatile("ld.shared.b32 %0, [%1];" : "=r"(alo[ma][3]) : "r"(aL + r8 + c1));
            }
            #pragma unroll
            for (int na = 0; na < 16; na++) {
                const uint32_t br = (uint32_t)(wn * 128 + na * 8 + g) * 128u;
                uint32_t bh0, bh1, bl0, bl1;
                asm volatile("ld.shared.b32 %0, [%1];" : "=r"(bh0) : "r"(bH + br + c0));
                asm volatile("ld.shared.b32 %0, [%1];" : "=r"(bh1) : "r"(bH + br + c1));
                asm volatile("ld.shared.b32 %0, [%1];" : "=r"(bl0) : "r"(bL + br + c0));
                asm volatile("ld.shared.b32 %0, [%1];" : "=r"(bl1) : "r"(bL + br + c1));
                #pragma unroll
                for (int ma = 0; ma < 2; ma++) {
                    mma_bf16(acc[ma][na], ahi[ma], bh0, bh1);
                    mma_bf16(acc[ma][na], ahi[ma], bl0, bl1);
                    mma_bf16(acc[ma][na], alo[ma], bh0, bh1);
                }
            }
        }
        __syncthreads();
    }

    // ---- epilogue: regs -> smem stage (128 x 66 f32) -> coalesced STG + bias ----
    float* stage = (float*)(smem + SM_STAGE);
    #pragma unroll
    for (int cc = 0; cc < 4; cc++) {
        __syncthreads();
        if (wn == (cc >> 1)) {
            #pragma unroll
            for (int ma = 0; ma < 2; ma++) {
                #pragma unroll
                for (int nac = 0; nac < 8; nac++) {
                    const int na = (cc & 1) * 8 + nac;
                    const int r0 = wm * 32 + ma * 16 + g;
                    const int colc = nac * 8 + 2 * tig;
                    *reinterpret_cast<float2*>(stage + r0 * 66 + colc) =
                        make_float2(acc[ma][na][0], acc[ma][na][1]);
                    *reinterpret_cast<float2*>(stage + (r0 + 8) * 66 + colc) =
                        make_float2(acc[ma][na][2], acc[ma][na][3]);
                }
            }
        }
        __syncthreads();
        const int c = tid & 63, rb = tid >> 6;
        const float bias = b_s[cc * 64 + c];
        #pragma unroll 4
        for (int j = 0; j < 32; j++) {
            const int r = rb + j * 4;
            const int id = ids_s[r >> 4];
            if (id >= 0)
                out[(size_t)id * (M_ROWS * H_DIM) + (r & 15) * H_DIM + cc * 64 + c] =
                    stage[r * 66 + c] + bias;
        }
    }
}

// ---------------- launch ----------------
extern "C" void kernel_launch(void* const* d_in, const int* in_sizes, int n_in,
                              void* d_out, int out_size) {
    const float* x   = (const float*)d_in[0];
    const int*   cid = (const int*)d_in[1];
    const float* W   = (const float*)d_in[2];
    const float* b   = (const float*)d_in[3];
    float* out = (float*)d_out;

    const int N = in_sizes[0] / (M_ROWS * K_DIM);

    cudaFuncSetAttribute(gemm_kernel, cudaFuncAttributeMaxDynamicSharedMemorySize, SM_TOTAL);

    prep_kernel<<<1, 512>>>(cid, N);
    dim3 wgrid(H_DIM / 32, K_DIM / 32, NCAT);
    wconv_kernel<<<wgrid, dim3(32, 8)>>>(W);
    gemm_kernel<<<N / 8 + NCAT, 256, SM_TOTAL>>>(x, b, out);
}

// round 5
// speedup vs baseline: 2.2634x; 1.4583x over previous
#include <cuda_runtime.h>
#include <cuda_bf16.h>
#include <cstdint>

// CategorySpecificLinear on sm_103 family target (no tcgen05 in PTX target):
// out[n,m,h] = sum_k x[n,m,k] * W[cat[n],k,h] + b[cat[n],h]
// N=4096, M=16, K=256, H=256, 64 categories.
//
// R5: fused prep+wconv (parallel), ldmatrix fragment loads, cp.async-staged x.
// mma.sync.m16n8k16 bf16, 3-term split (xh*Wh + xh*Wl + xl*Wh), fp32 acc.

#define K_DIM   256
#define H_DIM   256
#define M_ROWS  16
#define MAX_N   4096
#define NCAT    64
#define MAX_TILES (MAX_N / 8 + NCAT)     // 576
#define KC      64

__device__ int g_pad_sorted[MAX_TILES * 8];
__device__ int g_tile_cat[MAX_TILES];
__device__ int g_num_tiles;
__device__ __nv_bfloat16 g_Wt_hi[NCAT * H_DIM * K_DIM];  // [cat][h][k]
__device__ __nv_bfloat16 g_Wt_lo[NCAT * H_DIM * K_DIM];

// ---------------- smem layout (bytes) ----------------
#define SM_IDS    0              // 8 ints
#define SM_BIAS   64             // 256 f32
#define SM_A_HI   2048           // 128x64 bf16 = 16KB
#define SM_A_LO   (SM_A_HI + 16384)
#define SM_B0     (SM_A_LO + 16384)    // per buf: hi 32KB + lo 32KB
#define SM_BUF_SZ 65536
#define SM_X      (SM_B0 + 2 * SM_BUF_SZ)   // 165888; 128x64 f32 = 32KB
#define SM_TOTAL  (SM_X + 32768)            // 198656
#define SM_STAGE  SM_A_HI        // epilogue: 128x66 f32 = 33792 (A + dead B0 head)

#define SWZ(row, c) (((uint32_t)(row)) * 128u + (((uint32_t)(c)) ^ ((((uint32_t)(row)) & 7u) << 4)))

__device__ __forceinline__ uint32_t smem_u32(const void* p) {
    uint32_t a;
    asm("{ .reg .u64 t; cvta.to.shared.u64 t, %1; cvt.u32.u64 %0, t; }" : "=r"(a) : "l"(p));
    return a;
}

#define CP_ASYNC16(dst, src) \
    asm volatile("cp.async.cg.shared.global [%0], [%1], 16;" :: "r"(dst), "l"(src) : "memory")
#define CP_COMMIT() asm volatile("cp.async.commit_group;" ::: "memory")
#define CP_WAIT0()  asm volatile("cp.async.wait_group 0;" ::: "memory")

#define LDSM_X4(r0, r1, r2, r3, addr) \
    asm volatile("ldmatrix.sync.aligned.m8n8.x4.shared.b16 {%0,%1,%2,%3}, [%4];" \
                 : "=r"(r0), "=r"(r1), "=r"(r2), "=r"(r3) : "r"(addr))

__device__ __forceinline__ void mma_bf16(float* d, const uint32_t* a, uint32_t b0, uint32_t b1) {
    asm volatile(
        "mma.sync.aligned.m16n8k16.row.col.f32.bf16.bf16.f32 "
        "{%0,%1,%2,%3}, {%4,%5,%6,%7}, {%8,%9}, {%0,%1,%2,%3};"
        : "+f"(d[0]), "+f"(d[1]), "+f"(d[2]), "+f"(d[3])
        : "r"(a[0]), "r"(a[1]), "r"(a[2]), "r"(a[3]), "r"(b0), "r"(b1));
}

// ---------------- Fused prep + wconv ----------------
// Blocks [0, 4096): W [cat][k][h] f32 -> Wt_{hi,lo} [cat][h][k] bf16 (32x32 tiles)
// Block 4096: decode cat_ids + counting sort into padded 8-sample tiles.
__global__ void __launch_bounds__(256)
prep_wconv_kernel(const float* __restrict__ W, const int* __restrict__ raw, int n) {
    if (blockIdx.x < 4096) {
        // ---- wconv ----
        __shared__ float tile[32][33];
        int bid = blockIdx.x;
        int cat = bid >> 6, ht = (bid >> 3) & 7, kt = bid & 7;
        int tx = threadIdx.x & 31, ty = threadIdx.x >> 5;   // (32, 8)
        const float* Wc = W + (size_t)cat * K_DIM * H_DIM;
        #pragma unroll
        for (int j = 0; j < 4; j++) {
            int k = kt * 32 + ty + j * 8, h = ht * 32 + tx;
            tile[ty + j * 8][tx] = Wc[k * H_DIM + h];
        }
        __syncthreads();
        size_t base = (size_t)cat * H_DIM * K_DIM;
        #pragma unroll
        for (int j = 0; j < 4; j++) {
            int h = ht * 32 + ty + j * 8, k = kt * 32 + tx;
            float v = tile[tx][ty + j * 8];
            __nv_bfloat16 hi = __float2bfloat16_rn(v);
            __nv_bfloat16 lo = __float2bfloat16_rn(v - __bfloat162float(hi));
            g_Wt_hi[base + (size_t)h * K_DIM + k] = hi;
            g_Wt_lo[base + (size_t)h * K_DIM + k] = lo;
        }
        return;
    }
    // ---- prep (one block, parallel) ----
    __shared__ int cnt[NCAT], curs[NCAT], nt[NCAT], toff[NCAT], oddnz;
    __shared__ int cats[MAX_N];
    int t = threadIdx.x;
    if (t == 0) oddnz = 0;
    if (t < NCAT) { cnt[t] = 0; curs[t] = 0; }
    __syncthreads();
    int local = 0;
    for (int i = t; i < n / 2; i += 256) local |= raw[2 * i + 1];
    if (local) atomicOr(&oddnz, 1);
    __syncthreads();
    bool is64 = (oddnz == 0);
    for (int i = t; i < n; i += 256) {
        int c = is64 ? raw[2 * i] : raw[i];
        cats[i] = c;
        atomicAdd(&cnt[c], 1);
    }
    for (int i = t; i < MAX_TILES * 8; i += 256) g_pad_sorted[i] = -1;
    __syncthreads();
    if (t < NCAT) nt[t] = (cnt[t] + 7) >> 3;
    __syncthreads();
    if (t < NCAT) {
        int po = 0;
        for (int c = 0; c < t; c++) po += nt[c];
        toff[t] = po;
        for (int tt = 0; tt < nt[t]; tt++) g_tile_cat[po + tt] = t;
        if (t == NCAT - 1) g_num_tiles = po + nt[t];
    }
    __syncthreads();
    for (int i = t; i < n; i += 256) {
        int c = cats[i];
        int p = atomicAdd(&curs[c], 1);
        g_pad_sorted[toff[c] * 8 + p] = i;
    }
}

// ---------------- GEMM ----------------
__global__ void __launch_bounds__(256, 1)
gemm_kernel(const float* __restrict__ x, const float* __restrict__ b,
            float* __restrict__ out) {
    extern __shared__ char smem[];
    const int tile = blockIdx.x;
    if (tile >= g_num_tiles) return;

    const uint32_t sbase = smem_u32(smem);
    const int tid = threadIdx.x;
    const int wid = tid >> 5, lid = tid & 31;
    const int wm = wid >> 1, wn = wid & 1;        // 4M x 2N warp grid
    const int cat = g_tile_cat[tile];

    int* ids_s = (int*)(smem + SM_IDS);
    float* b_s = (float*)(smem + SM_BIAS);
    if (tid < 8) ids_s[tid] = g_pad_sorted[tile * 8 + tid];
    b_s[tid] = b[cat * H_DIM + tid];
    __syncthreads();

    const __nv_bfloat16* WtH = g_Wt_hi + (size_t)cat * H_DIM * K_DIM;
    const __nv_bfloat16* WtL = g_Wt_lo + (size_t)cat * H_DIM * K_DIM;

    float acc[2][16][4];
    #pragma unroll
    for (int ma = 0; ma < 2; ma++)
        #pragma unroll
        for (int na = 0; na < 16; na++)
            #pragma unroll
            for (int r = 0; r < 4; r++) acc[ma][na][r] = 0.f;

    // ---- async loaders: B chunk (hi+lo, 64KB) and X chunk (32KB f32) ----
    auto issueB = [&](int kc, int buf) {
        const uint32_t bh = sbase + SM_B0 + buf * SM_BUF_SZ;
        const uint32_t bl = bh + 32768;
        const int k0 = kc * KC;
        #pragma unroll
        for (int j = 0; j < 8; j++) {
            int i = tid + j * 256;
            int row = i >> 3, u = i & 7;
            uint32_t off = SWZ(row, u * 16);
            const char* srcH = (const char*)(WtH + (size_t)row * K_DIM + k0) + u * 16;
            const char* srcL = (const char*)(WtL + (size_t)row * K_DIM + k0) + u * 16;
            CP_ASYNC16(bh + off, srcH);
            CP_ASYNC16(bl + off, srcL);
        }
    };
    auto issueX = [&](int kc) {
        const int k0 = kc * KC;
        #pragma unroll
        for (int j = 0; j < 8; j++) {            // 128 rows x 16 chunks of 16B
            int i = tid + j * 256;
            int row = i >> 4, u = i & 15;
            int id = ids_s[row >> 4];
            if (id < 0) id = 0;                  // padded rows: load something valid
            const char* src = (const char*)(x + (size_t)id * (M_ROWS * K_DIM)
                                            + (row & 15) * K_DIM + k0) + u * 16;
            CP_ASYNC16(sbase + SM_X + row * 256 + u * 16, src);
        }
    };
    // ---- convert staged X f32 -> A_hi/A_lo bf16 (swizzled) ----
    auto convertA = [&]() {
        const float* Xs = (const float*)(smem + SM_X);
        #pragma unroll
        for (int j = 0; j < 8; j++) {
            int i = tid + j * 256;
            int row = i >> 4, f4 = i & 15;
            float4 v = *reinterpret_cast<const float4*>(Xs + row * 64 + f4 * 4);
            __nv_bfloat16 hx = __float2bfloat16_rn(v.x), hy = __float2bfloat16_rn(v.y);
            __nv_bfloat16 hz = __float2bfloat16_rn(v.z), hw = __float2bfloat16_rn(v.w);
            __nv_bfloat162 h01 = __halves2bfloat162(hx, hy), h23 = __halves2bfloat162(hz, hw);
            __nv_bfloat162 l01 = __halves2bfloat162(
                __float2bfloat16_rn(v.x - __bfloat162float(hx)),
                __float2bfloat16_rn(v.y - __bfloat162float(hy)));
            __nv_bfloat162 l23 = __halves2bfloat162(
                __float2bfloat16_rn(v.z - __bfloat162float(hz)),
                __float2bfloat16_rn(v.w - __bfloat162float(hw)));
            uint32_t off = SWZ(row, f4 * 8);
            *reinterpret_cast<uint2*>(smem + SM_A_HI + off) =
                make_uint2(*(uint32_t*)&h01, *(uint32_t*)&h23);
            *reinterpret_cast<uint2*>(smem + SM_A_LO + off) =
                make_uint2(*(uint32_t*)&l01, *(uint32_t*)&l23);
        }
    };

    // lane-invariant ldmatrix address components
    const uint32_t s7 = (uint32_t)(lid & 7) << 4;
    const int tl = lid >> 3;
    const uint32_t arow = (uint32_t)(wm * 32 + (tl & 1) * 8 + (lid & 7));
    const uint32_t brow = (uint32_t)(wn * 128 + (tl & 1) * 8 + (lid & 7));
    const uint32_t colsel = (uint32_t)((tl >> 1) * 16);

    issueB(0, 0);
    issueX(0);
    CP_COMMIT();

    for (int kc = 0; kc < 4; kc++) {
        CP_WAIT0();
        __syncthreads();            // B(kc), X(kc) visible to all
        convertA();                 // X(kc) -> A smem
        __syncthreads();            // A visible; X consumed
        if (kc < 3) {
            issueB(kc + 1, (kc + 1) & 1);
            issueX(kc + 1);
            CP_COMMIT();
        }

        // ---- compute chunk kc ----
        const uint32_t aH = sbase + SM_A_HI, aL = sbase + SM_A_LO;
        const uint32_t bH = sbase + SM_B0 + (kc & 1) * SM_BUF_SZ;
        const uint32_t bL = bH + 32768;
        #pragma unroll
        for (int ks = 0; ks < 4; ks++) {
            const uint32_t col = ((uint32_t)(ks * 32) + colsel) ^ s7;
            uint32_t ahi[2][4], alo[2][4];
            #pragma unroll
            for (int ma = 0; ma < 2; ma++) {
                uint32_t aoff = (arow + ma * 16) * 128u + col;
                LDSM_X4(ahi[ma][0], ahi[ma][1], ahi[ma][2], ahi[ma][3], aH + aoff);
                LDSM_X4(alo[ma][0], alo[ma][1], alo[ma][2], alo[ma][3], aL + aoff);
            }
            #pragma unroll
            for (int nap = 0; nap < 8; nap++) {
                uint32_t boff = (brow + nap * 16) * 128u + col;
                uint32_t bh0, bh1, bh2, bh3, bl0, bl1, bl2, bl3;
                LDSM_X4(bh0, bh1, bh2, bh3, bH + boff);
                LDSM_X4(bl0, bl1, bl2, bl3, bL + boff);
                #pragma unroll
                for (int ma = 0; ma < 2; ma++) {
                    mma_bf16(acc[ma][nap * 2], ahi[ma], bh0, bh2);
                    mma_bf16(acc[ma][nap * 2], ahi[ma], bl0, bl2);
                    mma_bf16(acc[ma][nap * 2], alo[ma], bh0, bh2);
                    mma_bf16(acc[ma][nap * 2 + 1], ahi[ma], bh1, bh3);
                    mma_bf16(acc[ma][nap * 2 + 1], ahi[ma], bl1, bl3);
                    mma_bf16(acc[ma][nap * 2 + 1], alo[ma], bh1, bh3);
                }
            }
        }
        __syncthreads();            // compute done before A/X overwritten
    }

    // ---- epilogue: regs -> smem stage (128 x 66 f32) -> coalesced STG + bias ----
    const int g = lid >> 2, tig = lid & 3;
    float* stage = (float*)(smem + SM_STAGE);
    #pragma unroll
    for (int cc = 0; cc < 4; cc++) {
        __syncthreads();
        if (wn == (cc >> 1)) {
            #pragma unroll
            for (int ma = 0; ma < 2; ma++) {
                #pragma unroll
                for (int nac = 0; nac < 8; nac++) {
                    const int na = (cc & 1) * 8 + nac;
                    const int r0 = wm * 32 + ma * 16 + g;
                    const int colc = nac * 8 + 2 * tig;
                    *reinterpret_cast<float2*>(stage + r0 * 66 + colc) =
                        make_float2(acc[ma][na][0], acc[ma][na][1]);
                    *reinterpret_cast<float2*>(stage + (r0 + 8) * 66 + colc) =
                        make_float2(acc[ma][na][2], acc[ma][na][3]);
                }
            }
        }
        __syncthreads();
        const int c = tid & 63, rb = tid >> 6;
        const float bias = b_s[cc * 64 + c];
        #pragma unroll 4
        for (int j = 0; j < 32; j++) {
            const int r = rb + j * 4;
            const int id = ids_s[r >> 4];
            if (id >= 0)
                out[(size_t)id * (M_ROWS * H_DIM) + (r & 15) * H_DIM + cc * 64 + c] =
                    stage[r * 66 + c] + bias;
        }
    }
}

// ---------------- launch ----------------
extern "C" void kernel_launch(void* const* d_in, const int* in_sizes, int n_in,
                              void* d_out, int out_size) {
    const float* x   = (const float*)d_in[0];
    const int*   cid = (const int*)d_in[1];
    const float* W   = (const float*)d_in[2];
    const float* b   = (const float*)d_in[3];
    float* out = (float*)d_out;

    const int N = in_sizes[0] / (M_ROWS * K_DIM);

    cudaFuncSetAttribute(gemm_kernel, cudaFuncAttributeMaxDynamicSharedMemorySize, SM_TOTAL);

    prep_wconv_kernel<<<4097, 256>>>(W, cid, N);
    gemm_kernel<<<MAX_TILES, 256, SM_TOTAL>>>(x, b, out);
}

// round 6
// speedup vs baseline: 2.4713x; 1.0918x over previous
#include <cuda_runtime.h>
#include <cuda_bf16.h>
#include <cstdint>

// CategorySpecificLinear on sm_103 family target (no tcgen05 in PTX target):
// out[n,m,h] = sum_k x[n,m,k] * W[cat[n],k,h] + b[cat[n],h]
// N=4096, M=16, K=256, H=256, 64 categories.
//
// R6: 512-thread CTAs (16 warps, warp tile 32x64) for 2x warps/SM at same RF;
// persistent tile loop (no wave quantization); single-pass epilogue.
// mma.sync.m16n8k16 bf16, 3-term split (xh*Wh + xh*Wl + xl*Wh), fp32 acc.

#define K_DIM   256
#define H_DIM   256
#define M_ROWS  16
#define MAX_N   4096
#define NCAT    64
#define MAX_TILES (MAX_N / 8 + NCAT)     // 576
#define KC      64
#define NSM     152

__device__ int g_pad_sorted[MAX_TILES * 8];
__device__ int g_tile_cat[MAX_TILES];
__device__ int g_num_tiles;
__device__ __nv_bfloat16 g_Wt_hi[NCAT * H_DIM * K_DIM];  // [cat][h][k]
__device__ __nv_bfloat16 g_Wt_lo[NCAT * H_DIM * K_DIM];

// ---------------- smem layout (bytes) ----------------
#define SM_IDS    0              // 8 ints
#define SM_BIAS   64             // 256 f32
#define SM_A_HI   2048           // 128x64 bf16 = 16KB
#define SM_A_LO   (SM_A_HI + 16384)
#define SM_B0     (SM_A_LO + 16384)    // per buf: hi 32KB + lo 32KB
#define SM_BUF_SZ 65536
#define SM_X      (SM_B0 + 2 * SM_BUF_SZ)   // 165888; 128x64 f32 = 32KB
#define SM_TOTAL  (SM_X + 32768)            // 198656
// epilogue stage: 128 x 260 f32 = 133120 B, overlaps dead A+B region
#define SM_STAGE  SM_A_HI
#define STG_W     260

#define SWZ(row, c) (((uint32_t)(row)) * 128u + (((uint32_t)(c)) ^ ((((uint32_t)(row)) & 7u) << 4)))

__device__ __forceinline__ uint32_t smem_u32(const void* p) {
    uint32_t a;
    asm("{ .reg .u64 t; cvta.to.shared.u64 t, %1; cvt.u32.u64 %0, t; }" : "=r"(a) : "l"(p));
    return a;
}

#define CP_ASYNC16(dst, src) \
    asm volatile("cp.async.cg.shared.global [%0], [%1], 16;" :: "r"(dst), "l"(src) : "memory")
#define CP_COMMIT() asm volatile("cp.async.commit_group;" ::: "memory")
#define CP_WAIT0()  asm volatile("cp.async.wait_group 0;" ::: "memory")

#define LDSM_X4(r0, r1, r2, r3, addr) \
    asm volatile("ldmatrix.sync.aligned.m8n8.x4.shared.b16 {%0,%1,%2,%3}, [%4];" \
                 : "=r"(r0), "=r"(r1), "=r"(r2), "=r"(r3) : "r"(addr))

__device__ __forceinline__ void mma_bf16(float* d, const uint32_t* a, uint32_t b0, uint32_t b1) {
    asm volatile(
        "mma.sync.aligned.m16n8k16.row.col.f32.bf16.bf16.f32 "
        "{%0,%1,%2,%3}, {%4,%5,%6,%7}, {%8,%9}, {%0,%1,%2,%3};"
        : "+f"(d[0]), "+f"(d[1]), "+f"(d[2]), "+f"(d[3])
        : "r"(a[0]), "r"(a[1]), "r"(a[2]), "r"(a[3]), "r"(b0), "r"(b1));
}

// ---------------- Fused prep + wconv ----------------
__global__ void __launch_bounds__(256)
prep_wconv_kernel(const float* __restrict__ W, const int* __restrict__ raw, int n) {
    if (blockIdx.x < 4096) {
        __shared__ float tile[32][33];
        int bid = blockIdx.x;
        int cat = bid >> 6, ht = (bid >> 3) & 7, kt = bid & 7;
        int tx = threadIdx.x & 31, ty = threadIdx.x >> 5;   // (32, 8)
        const float* Wc = W + (size_t)cat * K_DIM * H_DIM;
        #pragma unroll
        for (int j = 0; j < 4; j++) {
            int k = kt * 32 + ty + j * 8, h = ht * 32 + tx;
            tile[ty + j * 8][tx] = Wc[k * H_DIM + h];
        }
        __syncthreads();
        size_t base = (size_t)cat * H_DIM * K_DIM;
        #pragma unroll
        for (int j = 0; j < 4; j++) {
            int h = ht * 32 + ty + j * 8, k = kt * 32 + tx;
            float v = tile[tx][ty + j * 8];
            __nv_bfloat16 hi = __float2bfloat16_rn(v);
            __nv_bfloat16 lo = __float2bfloat16_rn(v - __bfloat162float(hi));
            g_Wt_hi[base + (size_t)h * K_DIM + k] = hi;
            g_Wt_lo[base + (size_t)h * K_DIM + k] = lo;
        }
        return;
    }
    // ---- prep (one block) ----
    __shared__ int cnt[NCAT], curs[NCAT], nt[NCAT], toff[NCAT], oddnz;
    __shared__ int cats[MAX_N];
    int t = threadIdx.x;
    if (t == 0) oddnz = 0;
    if (t < NCAT) { cnt[t] = 0; curs[t] = 0; }
    __syncthreads();
    int local = 0;
    for (int i = t; i < n / 2; i += 256) local |= raw[2 * i + 1];
    if (local) atomicOr(&oddnz, 1);
    __syncthreads();
    bool is64 = (oddnz == 0);
    for (int i = t; i < n; i += 256) {
        int c = is64 ? raw[2 * i] : raw[i];
        cats[i] = c;
        atomicAdd(&cnt[c], 1);
    }
    for (int i = t; i < MAX_TILES * 8; i += 256) g_pad_sorted[i] = -1;
    __syncthreads();
    if (t < NCAT) nt[t] = (cnt[t] + 7) >> 3;
    __syncthreads();
    if (t < NCAT) {
        int po = 0;
        for (int c = 0; c < t; c++) po += nt[c];
        toff[t] = po;
        for (int tt = 0; tt < nt[t]; tt++) g_tile_cat[po + tt] = t;
        if (t == NCAT - 1) g_num_tiles = po + nt[t];
    }
    __syncthreads();
    for (int i = t; i < n; i += 256) {
        int c = cats[i];
        int p = atomicAdd(&curs[c], 1);
        g_pad_sorted[toff[c] * 8 + p] = i;
    }
}

// ---------------- GEMM (persistent, 512 threads) ----------------
__global__ void __launch_bounds__(512, 1)
gemm_kernel(const float* __restrict__ x, const float* __restrict__ b,
            float* __restrict__ out) {
    extern __shared__ char smem[];
    const uint32_t sbase = smem_u32(smem);
    const int tid = threadIdx.x;
    const int wid = tid >> 5, lid = tid & 31;
    const int wm = wid >> 2, wn = wid & 3;        // 4M x 4N warp grid
    const int g = lid >> 2, tig = lid & 3;

    int* ids_s = (int*)(smem + SM_IDS);
    float* b_s = (float*)(smem + SM_BIAS);

    // lane-invariant ldmatrix address components
    const uint32_t s7 = (uint32_t)(lid & 7) << 4;
    const int tl = lid >> 3;
    const uint32_t arow = (uint32_t)(wm * 32 + (tl & 1) * 8 + (lid & 7));
    const uint32_t brow = (uint32_t)(wn * 64 + (tl & 1) * 8 + (lid & 7));
    const uint32_t colsel = (uint32_t)((tl >> 1) * 16);

    const int ntiles = g_num_tiles;
    for (int tile = blockIdx.x; tile < ntiles; tile += gridDim.x) {
        __syncthreads();   // previous tile's epilogue fully consumed ids_s/b_s/stage
        const int cat = g_tile_cat[tile];
        if (tid < 8) ids_s[tid] = g_pad_sorted[tile * 8 + tid];
        if (tid < 256) b_s[tid] = b[cat * H_DIM + tid];
        __syncthreads();

        const __nv_bfloat16* WtH = g_Wt_hi + (size_t)cat * H_DIM * K_DIM;
        const __nv_bfloat16* WtL = g_Wt_lo + (size_t)cat * H_DIM * K_DIM;

        float acc[2][8][4];
        #pragma unroll
        for (int ma = 0; ma < 2; ma++)
            #pragma unroll
            for (int na = 0; na < 8; na++)
                #pragma unroll
                for (int r = 0; r < 4; r++) acc[ma][na][r] = 0.f;

        auto issueB = [&](int kc, int buf) {
            const uint32_t bh = sbase + SM_B0 + buf * SM_BUF_SZ;
            const uint32_t bl = bh + 32768;
            const int k0 = kc * KC;
            #pragma unroll
            for (int j = 0; j < 4; j++) {
                int i = tid + j * 512;
                int row = i >> 3, u = i & 7;
                uint32_t off = SWZ(row, u * 16);
                const char* srcH = (const char*)(WtH + (size_t)row * K_DIM + k0) + u * 16;
                const char* srcL = (const char*)(WtL + (size_t)row * K_DIM + k0) + u * 16;
                CP_ASYNC16(bh + off, srcH);
                CP_ASYNC16(bl + off, srcL);
            }
        };
        auto issueX = [&](int kc) {
            const int k0 = kc * KC;
            #pragma unroll
            for (int j = 0; j < 4; j++) {
                int i = tid + j * 512;
                int row = i >> 4, u = i & 15;
                int id = ids_s[row >> 4];
                if (id < 0) id = 0;
                const char* src = (const char*)(x + (size_t)id * (M_ROWS * K_DIM)
                                                + (row & 15) * K_DIM + k0) + u * 16;
                CP_ASYNC16(sbase + SM_X + row * 256 + u * 16, src);
            }
        };
        auto convertA = [&]() {
            const float* Xs = (const float*)(smem + SM_X);
            #pragma unroll
            for (int j = 0; j < 4; j++) {
                int i = tid + j * 512;
                int row = i >> 4, f4 = i & 15;
                float4 v = *reinterpret_cast<const float4*>(Xs + row * 64 + f4 * 4);
                __nv_bfloat16 hx = __float2bfloat16_rn(v.x), hy = __float2bfloat16_rn(v.y);
                __nv_bfloat16 hz = __float2bfloat16_rn(v.z), hw = __float2bfloat16_rn(v.w);
                __nv_bfloat162 h01 = __halves2bfloat162(hx, hy), h23 = __halves2bfloat162(hz, hw);
                __nv_bfloat162 l01 = __halves2bfloat162(
                    __float2bfloat16_rn(v.x - __bfloat162float(hx)),
                    __float2bfloat16_rn(v.y - __bfloat162float(hy)));
                __nv_bfloat162 l23 = __halves2bfloat162(
                    __float2bfloat16_rn(v.z - __bfloat162float(hz)),
                    __float2bfloat16_rn(v.w - __bfloat162float(hw)));
                uint32_t off = SWZ(row, f4 * 8);
                *reinterpret_cast<uint2*>(smem + SM_A_HI + off) =
                    make_uint2(*(uint32_t*)&h01, *(uint32_t*)&h23);
                *reinterpret_cast<uint2*>(smem + SM_A_LO + off) =
                    make_uint2(*(uint32_t*)&l01, *(uint32_t*)&l23);
            }
        };

        issueB(0, 0);
        issueX(0);
        CP_COMMIT();

        for (int kc = 0; kc < 4; kc++) {
            CP_WAIT0();
            __syncthreads();            // B(kc), X(kc) visible
            convertA();
            __syncthreads();            // A visible; X consumed
            if (kc < 3) {
                issueB(kc + 1, (kc + 1) & 1);
                issueX(kc + 1);
                CP_COMMIT();
            }

            const uint32_t aH = sbase + SM_A_HI, aL = sbase + SM_A_LO;
            const uint32_t bH = sbase + SM_B0 + (kc & 1) * SM_BUF_SZ;
            const uint32_t bL = bH + 32768;
            #pragma unroll
            for (int ks = 0; ks < 4; ks++) {
                const uint32_t col = ((uint32_t)(ks * 32) + colsel) ^ s7;
                uint32_t ahi[2][4], alo[2][4];
                #pragma unroll
                for (int ma = 0; ma < 2; ma++) {
                    uint32_t aoff = (arow + ma * 16) * 128u + col;
                    LDSM_X4(ahi[ma][0], ahi[ma][1], ahi[ma][2], ahi[ma][3], aH + aoff);
                    LDSM_X4(alo[ma][0], alo[ma][1], alo[ma][2], alo[ma][3], aL + aoff);
                }
                #pragma unroll
                for (int nap = 0; nap < 4; nap++) {
                    uint32_t boff = (brow + nap * 16) * 128u + col;
                    uint32_t bh0, bh1, bh2, bh3, bl0, bl1, bl2, bl3;
                    LDSM_X4(bh0, bh1, bh2, bh3, bH + boff);
                    LDSM_X4(bl0, bl1, bl2, bl3, bL + boff);
                    #pragma unroll
                    for (int ma = 0; ma < 2; ma++) {
                        mma_bf16(acc[ma][nap * 2], ahi[ma], bh0, bh2);
                        mma_bf16(acc[ma][nap * 2], ahi[ma], bl0, bl2);
                        mma_bf16(acc[ma][nap * 2], alo[ma], bh0, bh2);
                        mma_bf16(acc[ma][nap * 2 + 1], ahi[ma], bh1, bh3);
                        mma_bf16(acc[ma][nap * 2 + 1], ahi[ma], bl1, bl3);
                        mma_bf16(acc[ma][nap * 2 + 1], alo[ma], bh1, bh3);
                    }
                }
            }
            __syncthreads();            // compute done before A/X/B overwritten
        }

        // ---- epilogue: all warps -> full stage (128 x 260 f32) -> coalesced STG ----
        float* stage = (float*)(smem + SM_STAGE);
        #pragma unroll
        for (int ma = 0; ma < 2; ma++) {
            #pragma unroll
            for (int na = 0; na < 8; na++) {
                const int r0 = wm * 32 + ma * 16 + g;
                const int colc = wn * 64 + na * 8 + 2 * tig;
                *reinterpret_cast<float2*>(stage + r0 * STG_W + colc) =
                    make_float2(acc[ma][na][0], acc[ma][na][1]);
                *reinterpret_cast<float2*>(stage + (r0 + 8) * STG_W + colc) =
                    make_float2(acc[ma][na][2], acc[ma][na][3]);
            }
        }
        __syncthreads();
        #pragma unroll
        for (int p = 0; p < 16; p++) {
            const int idx = tid + p * 512;
            const int r = idx >> 6, c4 = idx & 63;
            const int id = ids_s[r >> 4];
            if (id >= 0) {
                float4 v = *reinterpret_cast<const float4*>(stage + r * STG_W + c4 * 4);
                float4 bv = *reinterpret_cast<const float4*>(b_s + c4 * 4);
                v.x += bv.x; v.y += bv.y; v.z += bv.z; v.w += bv.w;
                *reinterpret_cast<float4*>(out + (size_t)id * (M_ROWS * H_DIM)
                                           + (r & 15) * H_DIM + c4 * 4) = v;
            }
        }
    }
}

// ---------------- launch ----------------
extern "C" void kernel_launch(void* const* d_in, const int* in_sizes, int n_in,
                              void* d_out, int out_size) {
    const float* x   = (const float*)d_in[0];
    const int*   cid = (const int*)d_in[1];
    const float* W   = (const float*)d_in[2];
    const float* b   = (const float*)d_in[3];
    float* out = (float*)d_out;

    const int N = in_sizes[0] / (M_ROWS * K_DIM);

    cudaFuncSetAttribute(gemm_kernel, cudaFuncAttributeMaxDynamicSharedMemorySize, SM_TOTAL);

    prep_wconv_kernel<<<4097, 256>>>(W, cid, N);
    gemm_kernel<<<NSM, 512, SM_TOTAL>>>(x, b, out);
}

// round 7
// speedup vs baseline: 2.5461x; 1.0302x over previous
#include <cuda_runtime.h>
#include <cuda_bf16.h>
#include <cstdint>

// CategorySpecificLinear on sm_103 family target (no tcgen05 in PTX target):
// out[n,m,h] = sum_k x[n,m,k] * W[cat[n],k,h] + b[cat[n],h]
// N=4096, M=16, K=256, H=256, 64 categories.
//
// R7: barrier-minimal pipeline. Double-buffered A and B; convertA consumes the
// exact cp.async chunks the same thread issued (self-visibility after
// wait_group, no barrier needed) -> 1 syncthreads per K-chunk.
// mma.sync.m16n8k16 bf16, 3-term split (xh*Wh + xh*Wl + xl*Wh), fp32 acc.

#define K_DIM   256
#define H_DIM   256
#define M_ROWS  16
#define MAX_N   4096
#define NCAT    64
#define MAX_TILES (MAX_N / 8 + NCAT)     // 576
#define KC      64
#define NSM     152

__device__ int g_pad_sorted[MAX_TILES * 8];
__device__ int g_tile_cat[MAX_TILES];
__device__ int g_num_tiles;
__device__ __nv_bfloat16 g_Wt_hi[NCAT * H_DIM * K_DIM];  // [cat][h][k]
__device__ __nv_bfloat16 g_Wt_lo[NCAT * H_DIM * K_DIM];

// ---------------- smem layout (bytes) ----------------
#define SM_BIAS    0                 // 256 f32 = 1KB
#define SM_IDS     1024              // 8 ints
#define SM_A0      2048              // A buf: hi 16KB + lo 16KB = 32KB; x2 bufs
#define SM_ABUF_SZ 32768
#define SM_B       (SM_A0 + 2 * SM_ABUF_SZ)   // 67584; B buf: hi 32KB + lo 32KB; x2
#define SM_BBUF_SZ 65536
#define SM_X       (SM_B + 2 * SM_BBUF_SZ)    // 198656; 128x64 f32 = 32KB
#define SM_TOTAL   (SM_X + 32768)             // 231424
// epilogue stage: 128 x 260 f32 = 133120 B, overlays dead A+B head
#define SM_STAGE   SM_A0
#define STG_W      260

#define SWZ(row, c) (((uint32_t)(row)) * 128u + (((uint32_t)(c)) ^ ((((uint32_t)(row)) & 7u) << 4)))

__device__ __forceinline__ uint32_t smem_u32(const void* p) {
    uint32_t a;
    asm("{ .reg .u64 t; cvta.to.shared.u64 t, %1; cvt.u32.u64 %0, t; }" : "=r"(a) : "l"(p));
    return a;
}

#define CP_ASYNC16(dst, src) \
    asm volatile("cp.async.cg.shared.global [%0], [%1], 16;" :: "r"(dst), "l"(src) : "memory")
#define CP_COMMIT() asm volatile("cp.async.commit_group;" ::: "memory")
#define CP_WAIT0()  asm volatile("cp.async.wait_group 0;" ::: "memory")

#define LDSM_X4(r0, r1, r2, r3, addr) \
    asm volatile("ldmatrix.sync.aligned.m8n8.x4.shared.b16 {%0,%1,%2,%3}, [%4];" \
                 : "=r"(r0), "=r"(r1), "=r"(r2), "=r"(r3) : "r"(addr))

__device__ __forceinline__ void mma_bf16(float* d, const uint32_t* a, uint32_t b0, uint32_t b1) {
    asm volatile(
        "mma.sync.aligned.m16n8k16.row.col.f32.bf16.bf16.f32 "
        "{%0,%1,%2,%3}, {%4,%5,%6,%7}, {%8,%9}, {%0,%1,%2,%3};"
        : "+f"(d[0]), "+f"(d[1]), "+f"(d[2]), "+f"(d[3])
        : "r"(a[0]), "r"(a[1]), "r"(a[2]), "r"(a[3]), "r"(b0), "r"(b1));
}

// ---------------- Fused prep + wconv ----------------
__global__ void __launch_bounds__(256)
prep_wconv_kernel(const float* __restrict__ W, const int* __restrict__ raw, int n) {
    if (blockIdx.x < 4096) {
        __shared__ float tile[32][33];
        int bid = blockIdx.x;
        int cat = bid >> 6, ht = (bid >> 3) & 7, kt = bid & 7;
        int tx = threadIdx.x & 31, ty = threadIdx.x >> 5;   // (32, 8)
        const float* Wc = W + (size_t)cat * K_DIM * H_DIM;
        #pragma unroll
        for (int j = 0; j < 4; j++) {
            int k = kt * 32 + ty + j * 8, h = ht * 32 + tx;
            tile[ty + j * 8][tx] = Wc[k * H_DIM + h];
        }
        __syncthreads();
        size_t base = (size_t)cat * H_DIM * K_DIM;
        #pragma unroll
        for (int j = 0; j < 4; j++) {
            int h = ht * 32 + ty + j * 8, k = kt * 32 + tx;
            float v = tile[tx][ty + j * 8];
            __nv_bfloat16 hi = __float2bfloat16_rn(v);
            __nv_bfloat16 lo = __float2bfloat16_rn(v - __bfloat162float(hi));
            g_Wt_hi[base + (size_t)h * K_DIM + k] = hi;
            g_Wt_lo[base + (size_t)h * K_DIM + k] = lo;
        }
        return;
    }
    // ---- prep (one block) ----
    __shared__ int cnt[NCAT], curs[NCAT], nt[NCAT], toff[NCAT], oddnz;
    __shared__ int cats[MAX_N];
    int t = threadIdx.x;
    if (t == 0) oddnz = 0;
    if (t < NCAT) { cnt[t] = 0; curs[t] = 0; }
    __syncthreads();
    int local = 0;
    for (int i = t; i < n / 2; i += 256) local |= raw[2 * i + 1];
    if (local) atomicOr(&oddnz, 1);
    __syncthreads();
    bool is64 = (oddnz == 0);
    for (int i = t; i < n; i += 256) {
        int c = is64 ? raw[2 * i] : raw[i];
        cats[i] = c;
        atomicAdd(&cnt[c], 1);
    }
    for (int i = t; i < MAX_TILES * 8; i += 256) g_pad_sorted[i] = -1;
    __syncthreads();
    if (t < NCAT) nt[t] = (cnt[t] + 7) >> 3;
    __syncthreads();
    if (t < NCAT) {
        int po = 0;
        for (int c = 0; c < t; c++) po += nt[c];
        toff[t] = po;
        for (int tt = 0; tt < nt[t]; tt++) g_tile_cat[po + tt] = t;
        if (t == NCAT - 1) g_num_tiles = po + nt[t];
    }
    __syncthreads();
    for (int i = t; i < n; i += 256) {
        int c = cats[i];
        int p = atomicAdd(&curs[c], 1);
        g_pad_sorted[toff[c] * 8 + p] = i;
    }
}

// ---------------- GEMM (persistent, 512 threads, barrier-minimal) ----------------
__global__ void __launch_bounds__(512, 1)
gemm_kernel(const float* __restrict__ x, const float* __restrict__ b,
            float* __restrict__ out) {
    extern __shared__ char smem[];
    const uint32_t sbase = smem_u32(smem);
    const int tid = threadIdx.x;
    const int wid = tid >> 5, lid = tid & 31;
    const int wm = wid >> 2, wn = wid & 3;        // 4M x 4N warp grid
    const int g = lid >> 2, tig = lid & 3;

    int* ids_s = (int*)(smem + SM_IDS);
    float* b_s = (float*)(smem + SM_BIAS);

    // lane-invariant ldmatrix address components
    const uint32_t s7 = (uint32_t)(lid & 7) << 4;
    const int tl = lid >> 3;
    const uint32_t arow = (uint32_t)(wm * 32 + (tl & 1) * 8 + (lid & 7));
    const uint32_t brow = (uint32_t)(wn * 64 + (tl & 1) * 8 + (lid & 7));
    const uint32_t colsel = (uint32_t)((tl >> 1) * 16);

    const int ntiles = g_num_tiles;
    for (int tile = blockIdx.x; tile < ntiles; tile += gridDim.x) {
        __syncthreads();   // prev tile's epilogue (stage/ids/bias reads) done
        const int cat = g_tile_cat[tile];
        if (tid < 8) ids_s[tid] = g_pad_sorted[tile * 8 + tid];
        if (tid < 256) b_s[tid] = b[cat * H_DIM + tid];

        const __nv_bfloat16* WtH = g_Wt_hi + (size_t)cat * H_DIM * K_DIM;
        const __nv_bfloat16* WtL = g_Wt_lo + (size_t)cat * H_DIM * K_DIM;

        float acc[2][8][4];
        #pragma unroll
        for (int ma = 0; ma < 2; ma++)
            #pragma unroll
            for (int na = 0; na < 8; na++)
                #pragma unroll
                for (int r = 0; r < 4; r++) acc[ma][na][r] = 0.f;

        auto issueB = [&](int kc) {
            const uint32_t bh = sbase + SM_B + (kc & 1) * SM_BBUF_SZ;
            const uint32_t bl = bh + 32768;
            const int k0 = kc * KC;
            #pragma unroll
            for (int j = 0; j < 4; j++) {
                int i = tid + j * 512;
                int row = i >> 3, u = i & 7;
                uint32_t off = SWZ(row, u * 16);
                const char* srcH = (const char*)(WtH + (size_t)row * K_DIM + k0) + u * 16;
                const char* srcL = (const char*)(WtL + (size_t)row * K_DIM + k0) + u * 16;
                CP_ASYNC16(bh + off, srcH);
                CP_ASYNC16(bl + off, srcL);
            }
        };
        auto issueX = [&](int kc) {
            const int k0 = kc * KC;
            #pragma unroll
            for (int j = 0; j < 4; j++) {
                int i = tid + j * 512;
                int row = i >> 4, u = i & 15;
                int id = __ldg(&g_pad_sorted[tile * 8 + (row >> 4)]);
                if (id < 0) id = 0;
                const char* src = (const char*)(x + (size_t)id * (M_ROWS * K_DIM)
                                                + (row & 15) * K_DIM + k0) + u * 16;
                CP_ASYNC16(sbase + SM_X + row * 256 + u * 16, src);
            }
        };
        // Convert: consumes EXACTLY the X chunks this thread cp.async'd
        // (same i = tid + j*512 mapping) -> valid right after CP_WAIT0, no barrier.
        auto convertA = [&](int abuf) {
            const float* Xs = (const float*)(smem + SM_X);
            const uint32_t aHb = sbase + SM_A0 + abuf * SM_ABUF_SZ;
            #pragma unroll
            for (int j = 0; j < 4; j++) {
                int i = tid + j * 512;
                int row = i >> 4, f4 = i & 15;
                float4 v = *reinterpret_cast<const float4*>(Xs + row * 64 + f4 * 4);
                __nv_bfloat16 hx = __float2bfloat16_rn(v.x), hy = __float2bfloat16_rn(v.y);
                __nv_bfloat16 hz = __float2bfloat16_rn(v.z), hw = __float2bfloat16_rn(v.w);
                __nv_bfloat162 h01 = __halves2bfloat162(hx, hy), h23 = __halves2bfloat162(hz, hw);
                __nv_bfloat162 l01 = __halves2bfloat162(
                    __float2bfloat16_rn(v.x - __bfloat162float(hx)),
                    __float2bfloat16_rn(v.y - __bfloat162float(hy)));
                __nv_bfloat162 l23 = __halves2bfloat162(
                    __float2bfloat16_rn(v.z - __bfloat162float(hz)),
                    __float2bfloat16_rn(v.w - __bfloat162float(hw)));
                uint32_t off = SWZ(row, f4 * 8);
                asm volatile("st.shared.v2.b32 [%0], {%1, %2};"
                             :: "r"(aHb + off), "r"(*(uint32_t*)&h01), "r"(*(uint32_t*)&h23)
                             : "memory");
                asm volatile("st.shared.v2.b32 [%0], {%1, %2};"
                             :: "r"(aHb + 16384 + off), "r"(*(uint32_t*)&l01), "r"(*(uint32_t*)&l23)
                             : "memory");
            }
        };
        auto compute = [&](int kc) {
            const uint32_t aH = sbase + SM_A0 + (kc & 1) * SM_ABUF_SZ;
            const uint32_t aL = aH + 16384;
            const uint32_t bH = sbase + SM_B + (kc & 1) * SM_BBUF_SZ;
            const uint32_t bL = bH + 32768;
            #pragma unroll
            for (int ks = 0; ks < 4; ks++) {
                const uint32_t col = ((uint32_t)(ks * 32) + colsel) ^ s7;
                uint32_t ahi[2][4], alo[2][4];
                #pragma unroll
                for (int ma = 0; ma < 2; ma++) {
                    uint32_t aoff = (arow + ma * 16) * 128u + col;
                    LDSM_X4(ahi[ma][0], ahi[ma][1], ahi[ma][2], ahi[ma][3], aH + aoff);
                    LDSM_X4(alo[ma][0], alo[ma][1], alo[ma][2], alo[ma][3], aL + aoff);
                }
                #pragma unroll
                for (int nap = 0; nap < 4; nap++) {
                    uint32_t boff = (brow + nap * 16) * 128u + col;
                    uint32_t bh0, bh1, bh2, bh3, bl0, bl1, bl2, bl3;
                    LDSM_X4(bh0, bh1, bh2, bh3, bH + boff);
                    LDSM_X4(bl0, bl1, bl2, bl3, bL + boff);
                    #pragma unroll
                    for (int ma = 0; ma < 2; ma++) {
                        mma_bf16(acc[ma][nap * 2], ahi[ma], bh0, bh2);
                        mma_bf16(acc[ma][nap * 2], ahi[ma], bl0, bl2);
                        mma_bf16(acc[ma][nap * 2], alo[ma], bh0, bh2);
                        mma_bf16(acc[ma][nap * 2 + 1], ahi[ma], bh1, bh3);
                        mma_bf16(acc[ma][nap * 2 + 1], ahi[ma], bl1, bl3);
                        mma_bf16(acc[ma][nap * 2 + 1], alo[ma], bh1, bh3);
                    }
                }
            }
        };

        // ---- prologue ----
        issueB(0); issueX(0); CP_COMMIT();
        CP_WAIT0();
        convertA(0);                  // own chunks, no barrier needed
        __syncthreads();              // A0 + B0 + ids/bias visible to all
        issueB(1); issueX(1); CP_COMMIT();

        // ---- mainloop: 1 syncthreads per kc ----
        for (int kc = 0; kc < 4; kc++) {
            compute(kc);
            if (kc < 3) {
                CP_WAIT0();           // group(kc+1): self copies complete
                convertA((kc + 1) & 1);
                __syncthreads();      // A(kc+1), B(kc+1) visible; B(kc) consumed
                if (kc < 2) { issueB(kc + 2); issueX(kc + 2); CP_COMMIT(); }
            }
        }

        // ---- epilogue: regs -> stage (128 x 260 f32) -> coalesced STG ----
        __syncthreads();              // all compute done; A/B smem dead
        float* stage = (float*)(smem + SM_STAGE);
        #pragma unroll
        for (int ma = 0; ma < 2; ma++) {
            #pragma unroll
            for (int na = 0; na < 8; na++) {
                const int r0 = wm * 32 + ma * 16 + g;
                const int colc = wn * 64 + na * 8 + 2 * tig;
                *reinterpret_cast<float2*>(stage + r0 * STG_W + colc) =
                    make_float2(acc[ma][na][0], acc[ma][na][1]);
                *reinterpret_cast<float2*>(stage + (r0 + 8) * STG_W + colc) =
                    make_float2(acc[ma][na][2], acc[ma][na][3]);
            }
        }
        __syncthreads();
        #pragma unroll
        for (int p = 0; p < 16; p++) {
            const int idx = tid + p * 512;
            const int r = idx >> 6, c4 = idx & 63;
            const int id = ids_s[r >> 4];
            if (id >= 0) {
                float4 v = *reinterpret_cast<const float4*>(stage + r * STG_W + c4 * 4);
                float4 bv = *reinterpret_cast<const float4*>(b_s + c4 * 4);
                v.x += bv.x; v.y += bv.y; v.z += bv.z; v.w += bv.w;
                *reinterpret_cast<float4*>(out + (size_t)id * (M_ROWS * H_DIM)
                                           + (r & 15) * H_DIM + c4 * 4) = v;
            }
        }
    }
}

// ---------------- launch ----------------
extern "C" void kernel_launch(void* const* d_in, const int* in_sizes, int n_in,
                              void* d_out, int out_size) {
    const float* x   = (const float*)d_in[0];
    const int*   cid = (const int*)d_in[1];
    const float* W   = (const float*)d_in[2];
    const float* b   = (const float*)d_in[3];
    float* out = (float*)d_out;

    const int N = in_sizes[0] / (M_ROWS * K_DIM);

    cudaFuncSetAttribute(gemm_kernel, cudaFuncAttributeMaxDynamicSharedMemorySize, SM_TOTAL);

    prep_wconv_kernel<<<4097, 256>>>(W, cid, N);
    gemm_kernel<<<NSM, 512, SM_TOTAL>>>(x, b, out);
}

// round 8
// speedup vs baseline: 3.3150x; 1.3020x over previous
#include <cuda_runtime.h>
#include <cuda_fp16.h>
#include <cstdint>

// CategorySpecificLinear on sm_103 family target (no tcgen05 in PTX target):
// out[n,m,h] = sum_k x[n,m,k] * W[cat[n],k,h] + b[cat[n],h]
// N=4096, M=16, K=256, H=256, 64 categories.
//
// R8: fp16 2-term split. x = xh + xl (both fp16; exact to 2^-22), W -> single
// fp16 Wh (error 2^-11). D = xh*Wh + xl*Wh = x_exact * Wh. 2 MMAs per
// fragment (was 3), B traffic halved. Term-major MMA ordering breaks the
// per-acc RAW chains. mma.sync.m16n8k16.f16, fp32 accumulate.

#define K_DIM   256
#define H_DIM   256
#define M_ROWS  16
#define MAX_N   4096
#define NCAT    64
#define MAX_TILES (MAX_N / 8 + NCAT)     // 576
#define KC      64
#define NSM     152

__device__ int g_pad_sorted[MAX_TILES * 8];
__device__ int g_tile_cat[MAX_TILES];
__device__ int g_num_tiles;
__device__ __half g_Wt[NCAT * H_DIM * K_DIM];   // [cat][h][k] fp16

// ---------------- smem layout (bytes) ----------------
#define SM_BIAS    0                 // 256 f32 = 1KB
#define SM_IDS     1024              // 8 ints
#define SM_A0      2048              // A buf: hi 16KB + lo 16KB = 32KB; x2 bufs
#define SM_ABUF_SZ 32768
#define SM_B       (SM_A0 + 2 * SM_ABUF_SZ)   // 67584; B buf: 32KB; x2
#define SM_BBUF_SZ 32768
#define SM_X       (SM_B + 2 * SM_BBUF_SZ)    // 133120; 128x64 f32 = 32KB
#define SM_TOTAL   (SM_X + 32768)             // 165888
// epilogue stage: 128 x 260 f32 = 133120 B, overlays dead A+B (+X head; X dead too)
#define SM_STAGE   SM_A0
#define STG_W      260

#define SWZ(row, c) (((uint32_t)(row)) * 128u + (((uint32_t)(c)) ^ ((((uint32_t)(row)) & 7u) << 4)))

__device__ __forceinline__ uint32_t smem_u32(const void* p) {
    uint32_t a;
    asm("{ .reg .u64 t; cvta.to.shared.u64 t, %1; cvt.u32.u64 %0, t; }" : "=r"(a) : "l"(p));
    return a;
}

#define CP_ASYNC16(dst, src) \
    asm volatile("cp.async.cg.shared.global [%0], [%1], 16;" :: "r"(dst), "l"(src) : "memory")
#define CP_COMMIT() asm volatile("cp.async.commit_group;" ::: "memory")
#define CP_WAIT0()  asm volatile("cp.async.wait_group 0;" ::: "memory")

#define LDSM_X4(r0, r1, r2, r3, addr) \
    asm volatile("ldmatrix.sync.aligned.m8n8.x4.shared.b16 {%0,%1,%2,%3}, [%4];" \
                 : "=r"(r0), "=r"(r1), "=r"(r2), "=r"(r3) : "r"(addr))

__device__ __forceinline__ void mma_f16(float* d, const uint32_t* a, uint32_t b0, uint32_t b1) {
    asm volatile(
        "mma.sync.aligned.m16n8k16.row.col.f32.f16.f16.f32 "
        "{%0,%1,%2,%3}, {%4,%5,%6,%7}, {%8,%9}, {%0,%1,%2,%3};"
        : "+f"(d[0]), "+f"(d[1]), "+f"(d[2]), "+f"(d[3])
        : "r"(a[0]), "r"(a[1]), "r"(a[2]), "r"(a[3]), "r"(b0), "r"(b1));
}

// ---------------- Fused prep + wconv ----------------
__global__ void __launch_bounds__(256)
prep_wconv_kernel(const float* __restrict__ W, const int* __restrict__ raw, int n) {
    if (blockIdx.x < 4096) {
        __shared__ float tile[32][33];
        int bid = blockIdx.x;
        int cat = bid >> 6, ht = (bid >> 3) & 7, kt = bid & 7;
        int tx = threadIdx.x & 31, ty = threadIdx.x >> 5;   // (32, 8)
        const float* Wc = W + (size_t)cat * K_DIM * H_DIM;
        #pragma unroll
        for (int j = 0; j < 4; j++) {
            int k = kt * 32 + ty + j * 8, h = ht * 32 + tx;
            tile[ty + j * 8][tx] = Wc[k * H_DIM + h];
        }
        __syncthreads();
        size_t base = (size_t)cat * H_DIM * K_DIM;
        #pragma unroll
        for (int j = 0; j < 4; j++) {
            int h = ht * 32 + ty + j * 8, k = kt * 32 + tx;
            g_Wt[base + (size_t)h * K_DIM + k] = __float2half_rn(tile[tx][ty + j * 8]);
        }
        return;
    }
    // ---- prep (one block) ----
    __shared__ int cnt[NCAT], curs[NCAT], nt[NCAT], toff[NCAT], oddnz;
    __shared__ int cats[MAX_N];
    int t = threadIdx.x;
    if (t == 0) oddnz = 0;
    if (t < NCAT) { cnt[t] = 0; curs[t] = 0; }
    __syncthreads();
    int local = 0;
    for (int i = t; i < n / 2; i += 256) local |= raw[2 * i + 1];
    if (local) atomicOr(&oddnz, 1);
    __syncthreads();
    bool is64 = (oddnz == 0);
    for (int i = t; i < n; i += 256) {
        int c = is64 ? raw[2 * i] : raw[i];
        cats[i] = c;
        atomicAdd(&cnt[c], 1);
    }
    for (int i = t; i < MAX_TILES * 8; i += 256) g_pad_sorted[i] = -1;
    __syncthreads();
    if (t < NCAT) nt[t] = (cnt[t] + 7) >> 3;
    __syncthreads();
    if (t < NCAT) {
        int po = 0;
        for (int c = 0; c < t; c++) po += nt[c];
        toff[t] = po;
        for (int tt = 0; tt < nt[t]; tt++) g_tile_cat[po + tt] = t;
        if (t == NCAT - 1) g_num_tiles = po + nt[t];
    }
    __syncthreads();
    for (int i = t; i < n; i += 256) {
        int c = cats[i];
        int p = atomicAdd(&curs[c], 1);
        g_pad_sorted[toff[c] * 8 + p] = i;
    }
}

// ---------------- GEMM (persistent, 512 threads) ----------------
__global__ void __launch_bounds__(512, 1)
gemm_kernel(const float* __restrict__ x, const float* __restrict__ b,
            float* __restrict__ out) {
    extern __shared__ char smem[];
    const uint32_t sbase = smem_u32(smem);
    const int tid = threadIdx.x;
    const int wid = tid >> 5, lid = tid & 31;
    const int wm = wid >> 2, wn = wid & 3;        // 4M x 4N warp grid
    const int g = lid >> 2, tig = lid & 3;

    int* ids_s = (int*)(smem + SM_IDS);
    float* b_s = (float*)(smem + SM_BIAS);

    // lane-invariant ldmatrix address components
    const uint32_t s7 = (uint32_t)(lid & 7) << 4;
    const int tl = lid >> 3;
    const uint32_t arow = (uint32_t)(wm * 32 + (tl & 1) * 8 + (lid & 7));
    const uint32_t brow = (uint32_t)(wn * 64 + (tl & 1) * 8 + (lid & 7));
    const uint32_t colsel = (uint32_t)((tl >> 1) * 16);

    const int ntiles = g_num_tiles;
    for (int tile = blockIdx.x; tile < ntiles; tile += gridDim.x) {
        __syncthreads();   // prev tile's epilogue reads done
        const int cat = g_tile_cat[tile];
        if (tid < 8) ids_s[tid] = g_pad_sorted[tile * 8 + tid];
        if (tid < 256) b_s[tid] = b[cat * H_DIM + tid];

        const __half* Wt = g_Wt + (size_t)cat * H_DIM * K_DIM;

        float acc[2][8][4];
        #pragma unroll
        for (int ma = 0; ma < 2; ma++)
            #pragma unroll
            for (int na = 0; na < 8; na++)
                #pragma unroll
                for (int r = 0; r < 4; r++) acc[ma][na][r] = 0.f;

        auto issueB = [&](int kc) {
            const uint32_t bb = sbase + SM_B + (kc & 1) * SM_BBUF_SZ;
            const int k0 = kc * KC;
            #pragma unroll
            for (int j = 0; j < 4; j++) {       // 256 rows x 8 x 16B = 2048 / 512
                int i = tid + j * 512;
                int row = i >> 3, u = i & 7;
                uint32_t off = SWZ(row, u * 16);
                const char* src = (const char*)(Wt + (size_t)row * K_DIM + k0) + u * 16;
                CP_ASYNC16(bb + off, src);
            }
        };
        auto issueX = [&](int kc) {
            const int k0 = kc * KC;
            #pragma unroll
            for (int j = 0; j < 4; j++) {
                int i = tid + j * 512;
                int row = i >> 4, u = i & 15;
                int id = __ldg(&g_pad_sorted[tile * 8 + (row >> 4)]);
                if (id < 0) id = 0;
                const char* src = (const char*)(x + (size_t)id * (M_ROWS * K_DIM)
                                                + (row & 15) * K_DIM + k0) + u * 16;
                CP_ASYNC16(sbase + SM_X + row * 256 + u * 16, src);
            }
        };
        // Convert consumes exactly the X chunks this thread issued (same index
        // mapping) -> valid right after CP_WAIT0, no barrier needed.
        auto convertA = [&](int abuf) {
            const float* Xs = (const float*)(smem + SM_X);
            const uint32_t aHb = sbase + SM_A0 + abuf * SM_ABUF_SZ;
            #pragma unroll
            for (int j = 0; j < 4; j++) {
                int i = tid + j * 512;
                int row = i >> 4, f4 = i & 15;
                float4 v = *reinterpret_cast<const float4*>(Xs + row * 64 + f4 * 4);
                __half hx = __float2half_rn(v.x), hy = __float2half_rn(v.y);
                __half hz = __float2half_rn(v.z), hw = __float2half_rn(v.w);
                __half2 h01 = __halves2half2(hx, hy), h23 = __halves2half2(hz, hw);
                __half2 l01 = __halves2half2(__float2half_rn(v.x - __half2float(hx)),
                                             __float2half_rn(v.y - __half2float(hy)));
                __half2 l23 = __halves2half2(__float2half_rn(v.z - __half2float(hz)),
                                             __float2half_rn(v.w - __half2float(hw)));
                uint32_t off = SWZ(row, f4 * 8);
                asm volatile("st.shared.v2.b32 [%0], {%1, %2};"
                             :: "r"(aHb + off), "r"(*(uint32_t*)&h01), "r"(*(uint32_t*)&h23)
                             : "memory");
                asm volatile("st.shared.v2.b32 [%0], {%1, %2};"
                             :: "r"(aHb + 16384 + off), "r"(*(uint32_t*)&l01), "r"(*(uint32_t*)&l23)
                             : "memory");
            }
        };
        auto compute = [&](int kc) {
            const uint32_t aH = sbase + SM_A0 + (kc & 1) * SM_ABUF_SZ;
            const uint32_t aL = aH + 16384;
            const uint32_t bB = sbase + SM_B + (kc & 1) * SM_BBUF_SZ;
            #pragma unroll
            for (int ks = 0; ks < 4; ks++) {
                const uint32_t col = ((uint32_t)(ks * 32) + colsel) ^ s7;
                uint32_t ahi[2][4], alo[2][4], bf[4][4];
                #pragma unroll
                for (int ma = 0; ma < 2; ma++) {
                    uint32_t aoff = (arow + ma * 16) * 128u + col;
                    LDSM_X4(ahi[ma][0], ahi[ma][1], ahi[ma][2], ahi[ma][3], aH + aoff);
                    LDSM_X4(alo[ma][0], alo[ma][1], alo[ma][2], alo[ma][3], aL + aoff);
                }
                #pragma unroll
                for (int nap = 0; nap < 4; nap++) {
                    uint32_t boff = (brow + nap * 16) * 128u + col;
                    LDSM_X4(bf[nap][0], bf[nap][1], bf[nap][2], bf[nap][3], bB + boff);
                }
                // term-major: all hi-term MMAs, then all lo-term MMAs.
                // Each acc touched once per term, 15 independent MMAs apart.
                #pragma unroll
                for (int nap = 0; nap < 4; nap++)
                    #pragma unroll
                    for (int ma = 0; ma < 2; ma++) {
                        mma_f16(acc[ma][nap * 2],     ahi[ma], bf[nap][0], bf[nap][2]);
                        mma_f16(acc[ma][nap * 2 + 1], ahi[ma], bf[nap][1], bf[nap][3]);
                    }
                #pragma unroll
                for (int nap = 0; nap < 4; nap++)
                    #pragma unroll
                    for (int ma = 0; ma < 2; ma++) {
                        mma_f16(acc[ma][nap * 2],     alo[ma], bf[nap][0], bf[nap][2]);
                        mma_f16(acc[ma][nap * 2 + 1], alo[ma], bf[nap][1], bf[nap][3]);
                    }
            }
        };

        // ---- prologue ----
        issueB(0); issueX(0); CP_COMMIT();
        CP_WAIT0();
        convertA(0);
        __syncthreads();              // A0 + B0 + ids/bias visible to all
        issueB(1); issueX(1); CP_COMMIT();

        // ---- mainloop: 1 syncthreads per kc ----
        for (int kc = 0; kc < 4; kc++) {
            compute(kc);
            if (kc < 3) {
                CP_WAIT0();
                convertA((kc + 1) & 1);
                __syncthreads();
                if (kc < 2) { issueB(kc + 2); issueX(kc + 2); CP_COMMIT(); }
            }
        }

        // ---- epilogue: regs -> stage (128 x 260 f32) -> coalesced STG ----
        __syncthreads();              // all compute done; A/B/X smem dead
        float* stage = (float*)(smem + SM_STAGE);
        #pragma unroll
        for (int ma = 0; ma < 2; ma++) {
            #pragma unroll
            for (int na = 0; na < 8; na++) {
                const int r0 = wm * 32 + ma * 16 + g;
                const int colc = wn * 64 + na * 8 + 2 * tig;
                *reinterpret_cast<float2*>(stage + r0 * STG_W + colc) =
                    make_float2(acc[ma][na][0], acc[ma][na][1]);
                *reinterpret_cast<float2*>(stage + (r0 + 8) * STG_W + colc) =
                    make_float2(acc[ma][na][2], acc[ma][na][3]);
            }
        }
        __syncthreads();
        #pragma unroll
        for (int p = 0; p < 16; p++) {
            const int idx = tid + p * 512;
            const int r = idx >> 6, c4 = idx & 63;
            const int id = ids_s[r >> 4];
            if (id >= 0) {
                float4 v = *reinterpret_cast<const float4*>(stage + r * STG_W + c4 * 4);
                float4 bv = *reinterpret_cast<const float4*>(b_s + c4 * 4);
                v.x += bv.x; v.y += bv.y; v.z += bv.z; v.w += bv.w;
                *reinterpret_cast<float4*>(out + (size_t)id * (M_ROWS * H_DIM)
                                           + (r & 15) * H_DIM + c4 * 4) = v;
            }
        }
    }
}

// ---------------- launch ----------------
extern "C" void kernel_launch(void* const* d_in, const int* in_sizes, int n_in,
                              void* d_out, int out_size) {
    const float* x   = (const float*)d_in[0];
    const int*   cid = (const int*)d_in[1];
    const float* W   = (const float*)d_in[2];
    const float* b   = (const float*)d_in[3];
    float* out = (float*)d_out;

    const int N = in_sizes[0] / (M_ROWS * K_DIM);

    cudaFuncSetAttribute(gemm_kernel, cudaFuncAttributeMaxDynamicSharedMemorySize, SM_TOTAL);

    prep_wconv_kernel<<<4097, 256>>>(W, cid, N);
    gemm_kernel<<<NSM, 512, SM_TOTAL>>>(x, b, out);
}

// round 9
// speedup vs baseline: 4.5926x; 1.3854x over previous
#include <cuda_runtime.h>
#include <cuda_fp16.h>
#include <cstdint>

// CategorySpecificLinear on sm_103 family target (no tcgen05 in PTX target):
// out[n,m,h] = sum_k x[n,m,k] * W[cat[n],k,h] + b[cat[n],h]
// N=4096, M=16, K=256, H=256, 64 categories.
//
// R9: pure fp16 GEMM (x -> fp16, W -> fp16), fp32 accumulate. Quantization
// errors add in quadrature: measured 2.07e-4 with W-only quant -> ~2.9e-4
// with both, still 3.4x under the 1e-3 threshold. Halves MMA count vs R8.

#define K_DIM   256
#define H_DIM   256
#define M_ROWS  16
#define MAX_N   4096
#define NCAT    64
#define MAX_TILES (MAX_N / 8 + NCAT)     // 576
#define KC      64
#define NSM     152

__device__ int g_pad_sorted[MAX_TILES * 8];
__device__ int g_tile_cat[MAX_TILES];
__device__ int g_num_tiles;
__device__ __half g_Wt[NCAT * H_DIM * K_DIM];   // [cat][h][k] fp16

// ---------------- smem layout (bytes) ----------------
#define SM_BIAS    0                 // 256 f32 = 1KB
#define SM_IDS     1024              // 8 ints
#define SM_A0      2048              // A buf: 128x64 fp16 = 16KB; x2 bufs
#define SM_ABUF_SZ 16384
#define SM_B       (SM_A0 + 2 * SM_ABUF_SZ)   // 34816; B buf: 256x64 fp16 = 32KB; x2
#define SM_BBUF_SZ 32768
#define SM_X       (SM_B + 2 * SM_BBUF_SZ)    // 100352; 128x64 f32 = 32KB
// epilogue stage: 128 x 260 f32 = 133120 B at SM_A0, overlays A+B+X (all dead)
#define SM_STAGE   SM_A0
#define STG_W      260
#define SM_TOTAL   (SM_A0 + 128 * STG_W * 4)  // 135168 (covers X end at 133120)

#define SWZ(row, c) (((uint32_t)(row)) * 128u + (((uint32_t)(c)) ^ ((((uint32_t)(row)) & 7u) << 4)))

__device__ __forceinline__ uint32_t smem_u32(const void* p) {
    uint32_t a;
    asm("{ .reg .u64 t; cvta.to.shared.u64 t, %1; cvt.u32.u64 %0, t; }" : "=r"(a) : "l"(p));
    return a;
}

#define CP_ASYNC16(dst, src) \
    asm volatile("cp.async.cg.shared.global [%0], [%1], 16;" :: "r"(dst), "l"(src) : "memory")
#define CP_COMMIT() asm volatile("cp.async.commit_group;" ::: "memory")
#define CP_WAIT0()  asm volatile("cp.async.wait_group 0;" ::: "memory")

#define LDSM_X4(r0, r1, r2, r3, addr) \
    asm volatile("ldmatrix.sync.aligned.m8n8.x4.shared.b16 {%0,%1,%2,%3}, [%4];" \
                 : "=r"(r0), "=r"(r1), "=r"(r2), "=r"(r3) : "r"(addr))

__device__ __forceinline__ void mma_f16(float* d, const uint32_t* a, uint32_t b0, uint32_t b1) {
    asm volatile(
        "mma.sync.aligned.m16n8k16.row.col.f32.f16.f16.f32 "
        "{%0,%1,%2,%3}, {%4,%5,%6,%7}, {%8,%9}, {%0,%1,%2,%3};"
        : "+f"(d[0]), "+f"(d[1]), "+f"(d[2]), "+f"(d[3])
        : "r"(a[0]), "r"(a[1]), "r"(a[2]), "r"(a[3]), "r"(b0), "r"(b1));
}

// ---------------- Fused prep + wconv ----------------
__global__ void __launch_bounds__(256)
prep_wconv_kernel(const float* __restrict__ W, const int* __restrict__ raw, int n) {
    if (blockIdx.x < 4096) {
        __shared__ float tile[32][33];
        int bid = blockIdx.x;
        int cat = bid >> 6, ht = (bid >> 3) & 7, kt = bid & 7;
        int tx = threadIdx.x & 31, ty = threadIdx.x >> 5;   // (32, 8)
        const float* Wc = W + (size_t)cat * K_DIM * H_DIM;
        #pragma unroll
        for (int j = 0; j < 4; j++) {
            int k = kt * 32 + ty + j * 8, h = ht * 32 + tx;
            tile[ty + j * 8][tx] = Wc[k * H_DIM + h];
        }
        __syncthreads();
        size_t base = (size_t)cat * H_DIM * K_DIM;
        #pragma unroll
        for (int j = 0; j < 4; j++) {
            int h = ht * 32 + ty + j * 8, k = kt * 32 + tx;
            g_Wt[base + (size_t)h * K_DIM + k] = __float2half_rn(tile[tx][ty + j * 8]);
        }
        return;
    }
    // ---- prep (one block) ----
    __shared__ int cnt[NCAT], curs[NCAT], nt[NCAT], toff[NCAT], oddnz;
    __shared__ int cats[MAX_N];
    int t = threadIdx.x;
    if (t == 0) oddnz = 0;
    if (t < NCAT) { cnt[t] = 0; curs[t] = 0; }
    __syncthreads();
    int local = 0;
    for (int i = t; i < n / 2; i += 256) local |= raw[2 * i + 1];
    if (local) atomicOr(&oddnz, 1);
    __syncthreads();
    bool is64 = (oddnz == 0);
    for (int i = t; i < n; i += 256) {
        int c = is64 ? raw[2 * i] : raw[i];
        cats[i] = c;
        atomicAdd(&cnt[c], 1);
    }
    for (int i = t; i < MAX_TILES * 8; i += 256) g_pad_sorted[i] = -1;
    __syncthreads();
    if (t < NCAT) nt[t] = (cnt[t] + 7) >> 3;
    __syncthreads();
    if (t < NCAT) {
        int po = 0;
        for (int c = 0; c < t; c++) po += nt[c];
        toff[t] = po;
        for (int tt = 0; tt < nt[t]; tt++) g_tile_cat[po + tt] = t;
        if (t == NCAT - 1) g_num_tiles = po + nt[t];
    }
    __syncthreads();
    for (int i = t; i < n; i += 256) {
        int c = cats[i];
        int p = atomicAdd(&curs[c], 1);
        g_pad_sorted[toff[c] * 8 + p] = i;
    }
}

// ---------------- GEMM (persistent, 512 threads) ----------------
__global__ void __launch_bounds__(512, 1)
gemm_kernel(const float* __restrict__ x, const float* __restrict__ b,
            float* __restrict__ out) {
    extern __shared__ char smem[];
    const uint32_t sbase = smem_u32(smem);
    const int tid = threadIdx.x;
    const int wid = tid >> 5, lid = tid & 31;
    const int wm = wid >> 2, wn = wid & 3;        // 4M x 4N warp grid
    const int g = lid >> 2, tig = lid & 3;

    int* ids_s = (int*)(smem + SM_IDS);
    float* b_s = (float*)(smem + SM_BIAS);

    // lane-invariant ldmatrix address components
    const uint32_t s7 = (uint32_t)(lid & 7) << 4;
    const int tl = lid >> 3;
    const uint32_t arow = (uint32_t)(wm * 32 + (tl & 1) * 8 + (lid & 7));
    const uint32_t brow = (uint32_t)(wn * 64 + (tl & 1) * 8 + (lid & 7));
    const uint32_t colsel = (uint32_t)((tl >> 1) * 16);

    const int ntiles = g_num_tiles;
    for (int tile = blockIdx.x; tile < ntiles; tile += gridDim.x) {
        __syncthreads();   // prev tile's epilogue reads done
        const int cat = g_tile_cat[tile];
        if (tid < 8) ids_s[tid] = g_pad_sorted[tile * 8 + tid];
        if (tid < 256) b_s[tid] = b[cat * H_DIM + tid];

        const __half* Wt = g_Wt + (size_t)cat * H_DIM * K_DIM;

        float acc[2][8][4];
        #pragma unroll
        for (int ma = 0; ma < 2; ma++)
            #pragma unroll
            for (int na = 0; na < 8; na++)
                #pragma unroll
                for (int r = 0; r < 4; r++) acc[ma][na][r] = 0.f;

        auto issueB = [&](int kc) {
            const uint32_t bb = sbase + SM_B + (kc & 1) * SM_BBUF_SZ;
            const int k0 = kc * KC;
            #pragma unroll
            for (int j = 0; j < 4; j++) {       // 256 rows x 8 x 16B = 2048 / 512
                int i = tid + j * 512;
                int row = i >> 3, u = i & 7;
                uint32_t off = SWZ(row, u * 16);
                const char* src = (const char*)(Wt + (size_t)row * K_DIM + k0) + u * 16;
                CP_ASYNC16(bb + off, src);
            }
        };
        auto issueX = [&](int kc) {
            const int k0 = kc * KC;
            #pragma unroll
            for (int j = 0; j < 4; j++) {
                int i = tid + j * 512;
                int row = i >> 4, u = i & 15;
                int id = __ldg(&g_pad_sorted[tile * 8 + (row >> 4)]);
                if (id < 0) id = 0;
                const char* src = (const char*)(x + (size_t)id * (M_ROWS * K_DIM)
                                                + (row & 15) * K_DIM + k0) + u * 16;
                CP_ASYNC16(sbase + SM_X + row * 256 + u * 16, src);
            }
        };
        // Convert consumes exactly the X chunks this thread issued (same index
        // mapping) -> valid right after CP_WAIT0, no barrier needed.
        auto convertA = [&](int abuf) {
            const float* Xs = (const float*)(smem + SM_X);
            const uint32_t ab = sbase + SM_A0 + abuf * SM_ABUF_SZ;
            #pragma unroll
            for (int j = 0; j < 4; j++) {
                int i = tid + j * 512;
                int row = i >> 4, f4 = i & 15;
                float4 v = *reinterpret_cast<const float4*>(Xs + row * 64 + f4 * 4);
                __half2 h01 = __halves2half2(__float2half_rn(v.x), __float2half_rn(v.y));
                __half2 h23 = __halves2half2(__float2half_rn(v.z), __float2half_rn(v.w));
                uint32_t off = SWZ(row, f4 * 8);
                asm volatile("st.shared.v2.b32 [%0], {%1, %2};"
                             :: "r"(ab + off), "r"(*(uint32_t*)&h01), "r"(*(uint32_t*)&h23)
                             : "memory");
            }
        };
        auto compute = [&](int kc) {
            const uint32_t aB = sbase + SM_A0 + (kc & 1) * SM_ABUF_SZ;
            const uint32_t bB = sbase + SM_B + (kc & 1) * SM_BBUF_SZ;
            #pragma unroll
            for (int ks = 0; ks < 4; ks++) {
                const uint32_t col = ((uint32_t)(ks * 32) + colsel) ^ s7;
                uint32_t af[2][4], bf[4][4];
                #pragma unroll
                for (int ma = 0; ma < 2; ma++) {
                    uint32_t aoff = (arow + ma * 16) * 128u + col;
                    LDSM_X4(af[ma][0], af[ma][1], af[ma][2], af[ma][3], aB + aoff);
                }
                #pragma unroll
                for (int nap = 0; nap < 4; nap++) {
                    uint32_t boff = (brow + nap * 16) * 128u + col;
                    LDSM_X4(bf[nap][0], bf[nap][1], bf[nap][2], bf[nap][3], bB + boff);
                }
                // each acc touched exactly once per ks -> 16 independent MMAs
                #pragma unroll
                for (int nap = 0; nap < 4; nap++)
                    #pragma unroll
                    for (int ma = 0; ma < 2; ma++) {
                        mma_f16(acc[ma][nap * 2],     af[ma], bf[nap][0], bf[nap][2]);
                        mma_f16(acc[ma][nap * 2 + 1], af[ma], bf[nap][1], bf[nap][3]);
                    }
            }
        };

        // ---- prologue ----
        issueB(0); issueX(0); CP_COMMIT();
        CP_WAIT0();
        convertA(0);
        __syncthreads();              // A0 + B0 + ids/bias visible to all
        issueB(1); issueX(1); CP_COMMIT();

        // ---- mainloop: 1 syncthreads per kc ----
        for (int kc = 0; kc < 4; kc++) {
            compute(kc);
            if (kc < 3) {
                CP_WAIT0();
                convertA((kc + 1) & 1);
                __syncthreads();
                if (kc < 2) { issueB(kc + 2); issueX(kc + 2); CP_COMMIT(); }
            }
        }

        // ---- epilogue: regs -> stage (128 x 260 f32) -> coalesced STG ----
        __syncthreads();              // all compute done; A/B/X smem dead
        float* stage = (float*)(smem + SM_STAGE);
        #pragma unroll
        for (int ma = 0; ma < 2; ma++) {
            #pragma unroll
            for (int na = 0; na < 8; na++) {
                const int r0 = wm * 32 + ma * 16 + g;
                const int colc = wn * 64 + na * 8 + 2 * tig;
                *reinterpret_cast<float2*>(stage + r0 * STG_W + colc) =
                    make_float2(acc[ma][na][0], acc[ma][na][1]);
                *reinterpret_cast<float2*>(stage + (r0 + 8) * STG_W + colc) =
                    make_float2(acc[ma][na][2], acc[ma][na][3]);
            }
        }
        __syncthreads();
        #pragma unroll
        for (int p = 0; p < 16; p++) {
            const int idx = tid + p * 512;
            const int r = idx >> 6, c4 = idx & 63;
            const int id = ids_s[r >> 4];
            if (id >= 0) {
                float4 v = *reinterpret_cast<const float4*>(stage + r * STG_W + c4 * 4);
                float4 bv = *reinterpret_cast<const float4*>(b_s + c4 * 4);
                v.x += bv.x; v.y += bv.y; v.z += bv.z; v.w += bv.w;
                *reinterpret_cast<float4*>(out + (size_t)id * (M_ROWS * H_DIM)
                                           + (r & 15) * H_DIM + c4 * 4) = v;
            }
        }
    }
}

// ---------------- launch ----------------
extern "C" void kernel_launch(void* const* d_in, const int* in_sizes, int n_in,
                              void* d_out, int out_size) {
    const float* x   = (const float*)d_in[0];
    const int*   cid = (const int*)d_in[1];
    const float* W   = (const float*)d_in[2];
    const float* b   = (const float*)d_in[3];
    float* out = (float*)d_out;

    const int N = in_sizes[0] / (M_ROWS * K_DIM);

    cudaFuncSetAttribute(gemm_kernel, cudaFuncAttributeMaxDynamicSharedMemorySize, SM_TOTAL);

    prep_wconv_kernel<<<4097, 256>>>(W, cid, N);
    gemm_kernel<<<NSM, 512, SM_TOTAL>>>(x, b, out);
}

// round 10
// speedup vs baseline: 4.7767x; 1.0401x over previous
#include <cuda_runtime.h>
#include <cuda_fp16.h>
#include <cstdint>

// CategorySpecificLinear on sm_103 family target (no tcgen05 in PTX target):
// out[n,m,h] = sum_k x[n,m,k] * W[cat[n],k,h] + b[cat[n],h]
// N=4096, M=16, K=256, H=256, 64 categories.
//
// R10: fp16 mma.sync GEMM (rel_err ~2.9e-4, calibrated). New this round:
//  - fast wconv (64x64 vectorized transpose tiles)
//  - direct-STG epilogue (no smem stage, no epilogue barriers)
//  - cross-tile prefetch of B0/X0 during epilogue (hides cold-X DRAM wait)
//  - 4 barriers/tile (was 7)

#define K_DIM   256
#define H_DIM   256
#define M_ROWS  16
#define MAX_N   4096
#define NCAT    64
#define MAX_TILES (MAX_N / 8 + NCAT)     // 576
#define KC      64
#define NSM     152

__device__ int g_pad_sorted[MAX_TILES * 8];
__device__ int g_tile_cat[MAX_TILES];
__device__ int g_num_tiles;
__device__ __half g_Wt[NCAT * H_DIM * K_DIM];   // [cat][h][k] fp16

// ---------------- smem layout (bytes) ----------------
#define SM_A0      0                  // A buf: 128x64 fp16 = 16KB; x2
#define SM_ABUF_SZ 16384
#define SM_B       32768              // B buf: 256x64 fp16 = 32KB; x2
#define SM_BBUF_SZ 32768
#define SM_X       98304              // 128x64 f32 = 32KB
#define SM_TOTAL   131072

#define SWZ(row, c) (((uint32_t)(row)) * 128u + (((uint32_t)(c)) ^ ((((uint32_t)(row)) & 7u) << 4)))

__device__ __forceinline__ uint32_t smem_u32(const void* p) {
    uint32_t a;
    asm("{ .reg .u64 t; cvta.to.shared.u64 t, %1; cvt.u32.u64 %0, t; }" : "=r"(a) : "l"(p));
    return a;
}

#define CP_ASYNC16(dst, src) \
    asm volatile("cp.async.cg.shared.global [%0], [%1], 16;" :: "r"(dst), "l"(src) : "memory")
#define CP_COMMIT() asm volatile("cp.async.commit_group;" ::: "memory")
#define CP_WAIT0()  asm volatile("cp.async.wait_group 0;" ::: "memory")

#define LDSM_X4(r0, r1, r2, r3, addr) \
    asm volatile("ldmatrix.sync.aligned.m8n8.x4.shared.b16 {%0,%1,%2,%3}, [%4];" \
                 : "=r"(r0), "=r"(r1), "=r"(r2), "=r"(r3) : "r"(addr))

__device__ __forceinline__ void mma_f16(float* d, const uint32_t* a, uint32_t b0, uint32_t b1) {
    asm volatile(
        "mma.sync.aligned.m16n8k16.row.col.f32.f16.f16.f32 "
        "{%0,%1,%2,%3}, {%4,%5,%6,%7}, {%8,%9}, {%0,%1,%2,%3};"
        : "+f"(d[0]), "+f"(d[1]), "+f"(d[2]), "+f"(d[3])
        : "r"(a[0]), "r"(a[1]), "r"(a[2]), "r"(a[3]), "r"(b0), "r"(b1));
}

// ---------------- Fused prep + wconv ----------------
// Blocks [0,1024): W [cat][k][h] f32 -> g_Wt [cat][h][k] fp16, 64x64 tiles.
// Block 1024: decode cat_ids + counting sort into padded 8-sample tiles.
__global__ void __launch_bounds__(256)
prep_wconv_kernel(const float* __restrict__ W, const int* __restrict__ raw, int n) {
    if (blockIdx.x < 1024) {
        __shared__ float tile[64 * 65];     // [k_local][h_local], pad 65
        const int bid = blockIdx.x;
        const int cat = bid >> 4, ht = (bid >> 2) & 3, kt = bid & 3;
        const int tid = threadIdx.x;
        const float* Wc = W + ((size_t)cat * K_DIM + kt * 64) * H_DIM + ht * 64;
        // load 64 k-rows x 64 h (16 float4 per row)
        #pragma unroll
        for (int j = 0; j < 4; j++) {
            int i = tid + j * 256;
            int kk = i >> 4, f4 = i & 15;
            float4 v = *reinterpret_cast<const float4*>(Wc + (size_t)kk * H_DIM + f4 * 4);
            float* dst = tile + kk * 65 + f4 * 4;
            dst[0] = v.x; dst[1] = v.y; dst[2] = v.z; dst[3] = v.w;
        }
        __syncthreads();
        // write 64 h-rows x 64 k (8 x uint4 per row, 8 halves each)
        __half* Wo = g_Wt + ((size_t)cat * H_DIM + ht * 64) * K_DIM + kt * 64;
        #pragma unroll
        for (int j = 0; j < 2; j++) {
            int i = tid + j * 256;
            int hr = i >> 3, u = i & 7;
            __half tmp[8];
            #pragma unroll
            for (int c = 0; c < 8; c++)
                tmp[c] = __float2half_rn(tile[(u * 8 + c) * 65 + hr]);
            *reinterpret_cast<uint4*>(Wo + (size_t)hr * K_DIM + u * 8) =
                *reinterpret_cast<uint4*>(tmp);
        }
        return;
    }
    // ---- prep (one block) ----
    __shared__ int cnt[NCAT], curs[NCAT], nt[NCAT], toff[NCAT], oddnz;
    __shared__ int cats[MAX_N];
    int t = threadIdx.x;
    if (t == 0) oddnz = 0;
    if (t < NCAT) { cnt[t] = 0; curs[t] = 0; }
    __syncthreads();
    int local = 0;
    for (int i = t; i < n / 2; i += 256) local |= raw[2 * i + 1];
    if (local) atomicOr(&oddnz, 1);
    __syncthreads();
    bool is64 = (oddnz == 0);
    for (int i = t; i < n; i += 256) {
        int c = is64 ? raw[2 * i] : raw[i];
        cats[i] = c;
        atomicAdd(&cnt[c], 1);
    }
    for (int i = t; i < MAX_TILES * 8; i += 256) g_pad_sorted[i] = -1;
    __syncthreads();
    if (t < NCAT) nt[t] = (cnt[t] + 7) >> 3;
    __syncthreads();
    if (t < NCAT) {
        int po = 0;
        for (int c = 0; c < t; c++) po += nt[c];
        toff[t] = po;
        for (int tt = 0; tt < nt[t]; tt++) g_tile_cat[po + tt] = t;
        if (t == NCAT - 1) g_num_tiles = po + nt[t];
    }
    __syncthreads();
    for (int i = t; i < n; i += 256) {
        int c = cats[i];
        int p = atomicAdd(&curs[c], 1);
        g_pad_sorted[toff[c] * 8 + p] = i;
    }
}

// ---------------- GEMM (persistent, 512 threads) ----------------
__global__ void __launch_bounds__(512, 1)
gemm_kernel(const float* __restrict__ x, const float* __restrict__ b,
            float* __restrict__ out) {
    extern __shared__ char smem[];
    const uint32_t sbase = smem_u32(smem);
    const int tid = threadIdx.x;
    const int wid = tid >> 5, lid = tid & 31;
    const int wm = wid >> 2, wn = wid & 3;        // 4M x 4N warp grid
    const int g = lid >> 2, tig = lid & 3;

    // lane-invariant ldmatrix address components
    const uint32_t s7 = (uint32_t)(lid & 7) << 4;
    const int tl = lid >> 3;
    const uint32_t arow = (uint32_t)(wm * 32 + (tl & 1) * 8 + (lid & 7));
    const uint32_t brow = (uint32_t)(wn * 64 + (tl & 1) * 8 + (lid & 7));
    const uint32_t colsel = (uint32_t)((tl >> 1) * 16);

    auto issueB = [&](const __half* Wt, int kc) {
        const uint32_t bb = sbase + SM_B + (kc & 1) * SM_BBUF_SZ;
        const int k0 = kc * KC;
        #pragma unroll
        for (int j = 0; j < 4; j++) {       // 256 rows x 8 x 16B = 2048 / 512
            int i = tid + j * 512;
            int row = i >> 3, u = i & 7;
            uint32_t off = SWZ(row, u * 16);
            const char* src = (const char*)(Wt + (size_t)row * K_DIM + k0) + u * 16;
            CP_ASYNC16(bb + off, src);
        }
    };
    auto issueX = [&](int tl_idx, int kc) {
        const int k0 = kc * KC;
        #pragma unroll
        for (int j = 0; j < 4; j++) {
            int i = tid + j * 512;
            int row = i >> 4, u = i & 15;
            int id = __ldg(&g_pad_sorted[tl_idx * 8 + (row >> 4)]);
            if (id < 0) id = 0;
            const char* src = (const char*)(x + (size_t)id * (M_ROWS * K_DIM)
                                            + (row & 15) * K_DIM + k0) + u * 16;
            CP_ASYNC16(sbase + SM_X + row * 256 + u * 16, src);
        }
    };
    // Converts exactly the X chunks this thread issued -> valid right after
    // CP_WAIT0, no barrier needed before it.
    auto convertA = [&](int abuf) {
        const float* Xs = (const float*)(smem + SM_X);
        const uint32_t ab = sbase + SM_A0 + abuf * SM_ABUF_SZ;
        #pragma unroll
        for (int j = 0; j < 4; j++) {
            int i = tid + j * 512;
            int row = i >> 4, f4 = i & 15;
            float4 v = *reinterpret_cast<const float4*>(Xs + row * 64 + f4 * 4);
            __half2 h01 = __halves2half2(__float2half_rn(v.x), __float2half_rn(v.y));
            __half2 h23 = __halves2half2(__float2half_rn(v.z), __float2half_rn(v.w));
            uint32_t off = SWZ(row, f4 * 8);
            asm volatile("st.shared.v2.b32 [%0], {%1, %2};"
                         :: "r"(ab + off), "r"(*(uint32_t*)&h01), "r"(*(uint32_t*)&h23)
                         : "memory");
        }
    };

    const int ntiles = g_num_tiles;

    // prefetch first tile's chunk 0
    if ((int)blockIdx.x < ntiles) {
        const int cat0 = __ldg(&g_tile_cat[blockIdx.x]);
        issueB(g_Wt + (size_t)cat0 * H_DIM * K_DIM, 0);
        issueX(blockIdx.x, 0);
        CP_COMMIT();
    }

    for (int tile = blockIdx.x; tile < ntiles; tile += gridDim.x) {
        const int cat = __ldg(&g_tile_cat[tile]);
        const __half* Wt = g_Wt + (size_t)cat * H_DIM * K_DIM;

        float acc[2][8][4];
        #pragma unroll
        for (int ma = 0; ma < 2; ma++)
            #pragma unroll
            for (int na = 0; na < 8; na++)
                #pragma unroll
                for (int r = 0; r < 4; r++) acc[ma][na][r] = 0.f;

        auto compute = [&](int kc) {
            const uint32_t aB = sbase + SM_A0 + (kc & 1) * SM_ABUF_SZ;
            const uint32_t bB = sbase + SM_B + (kc & 1) * SM_BBUF_SZ;
            #pragma unroll
            for (int ks = 0; ks < 4; ks++) {
                const uint32_t col = ((uint32_t)(ks * 32) + colsel) ^ s7;
                uint32_t af[2][4], bf[4][4];
                #pragma unroll
                for (int ma = 0; ma < 2; ma++) {
                    uint32_t aoff = (arow + ma * 16) * 128u + col;
                    LDSM_X4(af[ma][0], af[ma][1], af[ma][2], af[ma][3], aB + aoff);
                }
                #pragma unroll
                for (int nap = 0; nap < 4; nap++) {
                    uint32_t boff = (brow + nap * 16) * 128u + col;
                    LDSM_X4(bf[nap][0], bf[nap][1], bf[nap][2], bf[nap][3], bB + boff);
                }
                #pragma unroll
                for (int nap = 0; nap < 4; nap++)
                    #pragma unroll
                    for (int ma = 0; ma < 2; ma++) {
                        mma_f16(acc[ma][nap * 2],     af[ma], bf[nap][0], bf[nap][2]);
                        mma_f16(acc[ma][nap * 2 + 1], af[ma], bf[nap][1], bf[nap][3]);
                    }
            }
        };

        // ---- tile prologue: chunk 0 arrived (prefetched during prev epilogue) ----
        CP_WAIT0();
        convertA(0);
        __syncthreads();              // A0 + B0 visible to all warps
        issueB(Wt, 1); issueX(tile, 1); CP_COMMIT();

        // ---- mainloop: 1 syncthreads per kc ----
        for (int kc = 0; kc < 4; kc++) {
            compute(kc);
            if (kc < 3) {
                CP_WAIT0();
                convertA((kc + 1) & 1);
                __syncthreads();
                if (kc < 2) { issueB(Wt, kc + 2); issueX(tile, kc + 2); CP_COMMIT(); }
            }
        }

        // ---- cross-tile prefetch: next tile's chunk 0 flies during epilogue ----
        {
            const int nx = tile + gridDim.x;
            if (nx < ntiles) {
                const int catn = __ldg(&g_tile_cat[nx]);
                issueB(g_Wt + (size_t)catn * H_DIM * K_DIM, 0);
                issueX(nx, 0);
                CP_COMMIT();
            }
        }

        // ---- epilogue: direct STG from fragments (32B sectors), bias via __ldg ----
        const float* bc = b + cat * H_DIM;
        #pragma unroll
        for (int ma = 0; ma < 2; ma++) {
            const int r0 = wm * 32 + ma * 16 + g;          // rows r0, r0+8 (same sample)
            const int id = __ldg(&g_pad_sorted[tile * 8 + (r0 >> 4)]);
            if (id >= 0) {
                float* o0 = out + (size_t)id * (M_ROWS * H_DIM) + (r0 & 15) * H_DIM;
                float* o8 = o0 + 8 * H_DIM;
                #pragma unroll
                for (int na = 0; na < 8; na++) {
                    const int colc = wn * 64 + na * 8 + 2 * tig;
                    const float2 bv = __ldg(reinterpret_cast<const float2*>(bc + colc));
                    *reinterpret_cast<float2*>(o0 + colc) =
                        make_float2(acc[ma][na][0] + bv.x, acc[ma][na][1] + bv.y);
                    *reinterpret_cast<float2*>(o8 + colc) =
                        make_float2(acc[ma][na][2] + bv.x, acc[ma][na][3] + bv.y);
                }
            }
        }
        // no barrier: epilogue touches only regs/global; buffer reuse is safe
        // (next convertA(0) writes abuf0, last read before the kc=2 barrier).
    }
}

// ---------------- launch ----------------
extern "C" void kernel_launch(void* const* d_in, const int* in_sizes, int n_in,
                              void* d_out, int out_size) {
    const float* x   = (const float*)d_in[0];
    const int*   cid = (const int*)d_in[1];
    const float* W   = (const float*)d_in[2];
    const float* b   = (const float*)d_in[3];
    float* out = (float*)d_out;

    const int N = in_sizes[0] / (M_ROWS * K_DIM);

    cudaFuncSetAttribute(gemm_kernel, cudaFuncAttributeMaxDynamicSharedMemorySize, SM_TOTAL);

    prep_wconv_kernel<<<1025, 256>>>(W, cid, N);
    gemm_kernel<<<NSM, 512, SM_TOTAL>>>(x, b, out);
}